// round 15
// baseline (speedup 1.0000x reference)
#include <cuda_runtime.h>
#include <cuda_bf16.h>
#include <math.h>
#include <stdint.h>

#define Bb   4
#define Tt   2048
#define Dd   1024
#define Hh   16
#define DhD  64
#define SEG  256
#define NSEG 8
#define BT   (Bb*Tt)      // 8192
#define BH   (Bb*Hh)      // 64

#define SWZ(o) ((o) ^ ((((o) >> 3)) & 0x70))

// idesc kind::f16 cg1: F32 accum, BF16 a/b, N=128, M=128
#define IDESC 0x8200490u

// tcgen05 is only available on arch-SPECIFIC targets (sm_103a / sm_100a).
#if defined(__CUDA_ARCH_FEAT_SM103_ALL) || defined(__CUDA_ARCH_FEAT_SM100_ALL) || defined(__CUDA_ARCH_SPECIFIC__)
#define TC_OK 1
#else
#define TC_OK 0
#endif

// ---------------- scratch (device globals; no allocations allowed) ----------
__device__ __align__(16) float g_q[BT*Dd];
__device__ __align__(16) float g_k[BT*Dd];
__device__ __align__(16) float g_v[BT*Dd];
__device__ __align__(16) float g_u[BT*Dd];
__device__ __align__(16) float g_y[BT*Dd];
__device__ __align__(16) float g_Sseg[BH*NSEG*DhD*DhD];
__device__ __align__(16) float g_cS  [BH*NSEG*DhD*DhD];
__device__ __align__(16) float g_cctx[BH*NSEG*DhD];

// bf16 split operands (weights stored TRANSPOSED: [N][K] K-major)
__device__ __align__(16) __nv_bfloat16 g_xhi[BT*Dd];
__device__ __align__(16) __nv_bfloat16 g_xlo[BT*Dd];
__device__ __align__(16) __nv_bfloat16 g_yhi[BT*Dd];
__device__ __align__(16) __nv_bfloat16 g_ylo[BT*Dd];
__device__ __align__(16) __nv_bfloat16 g_whi[5*Dd*Dd];
__device__ __align__(16) __nv_bfloat16 g_wlo[5*Dd*Dd];

// ---------------- small helpers ---------------------------------------------
__device__ __forceinline__ uint32_t smem_u32(const void* p) {
    uint32_t a;
    asm("{ .reg .u64 t; cvta.to.shared.u64 t, %1; cvt.u32.u64 %0, t; }"
        : "=r"(a) : "l"(p));
    return a;
}

__device__ __forceinline__ void cp16(uint32_t saddr, const void* gptr) {
    asm volatile("cp.async.cg.shared.global [%0], [%1], 16;"
                 :: "r"(saddr), "l"(gptr));
}

#if TC_OK
__device__ __forceinline__ void mma_f16_ss(uint32_t d, uint64_t ad, uint64_t bd,
                                           uint32_t idesc, uint32_t en) {
    asm volatile(
        "{\n\t.reg .pred p;\n\tsetp.ne.u32 p, %5, 0;\n\t"
        "tcgen05.mma.cta_group::1.kind::f16 [%0], %1, %2, %3, {%4,%4,%4,%4}, p;\n\t}"
        :: "r"(d), "l"(ad), "l"(bd), "r"(idesc), "r"(0u), "r"(en) : "memory");
}

__device__ __forceinline__ void mbar_wait(uint32_t mbar, int parity) {
    asm volatile(
        "{\n\t.reg .pred P;\n\t"
        "LAB_%=:\n\t"
        "mbarrier.try_wait.parity.acquire.cta.shared::cta.b64 P, [%0], %1;\n\t"
        "@!P bra LAB_%=;\n\t}"
        :: "r"(mbar), "r"(parity) : "memory");
}

__device__ __forceinline__ void ldtm32(uint32_t* r, uint32_t addr) {
    asm volatile(
        "tcgen05.ld.sync.aligned.32x32b.x32.b32 "
        "{%0, %1, %2, %3, %4, %5, %6, %7, "
        " %8, %9, %10, %11, %12, %13, %14, %15, "
        " %16, %17, %18, %19, %20, %21, %22, %23, "
        " %24, %25, %26, %27, %28, %29, %30, %31}, [%32];"
        : "=r"(r[0]),  "=r"(r[1]),  "=r"(r[2]),  "=r"(r[3]),
          "=r"(r[4]),  "=r"(r[5]),  "=r"(r[6]),  "=r"(r[7]),
          "=r"(r[8]),  "=r"(r[9]),  "=r"(r[10]), "=r"(r[11]),
          "=r"(r[12]), "=r"(r[13]), "=r"(r[14]), "=r"(r[15]),
          "=r"(r[16]), "=r"(r[17]), "=r"(r[18]), "=r"(r[19]),
          "=r"(r[20]), "=r"(r[21]), "=r"(r[22]), "=r"(r[23]),
          "=r"(r[24]), "=r"(r[25]), "=r"(r[26]), "=r"(r[27]),
          "=r"(r[28]), "=r"(r[29]), "=r"(r[30]), "=r"(r[31])
        : "r"(addr));
}
#endif

// ---------------- fp32 -> (bf16 hi, bf16 lo) split (activations, K-major) ---
__global__ __launch_bounds__(256) void cvt_split(
    const float4* __restrict__ in,
    __nv_bfloat16* __restrict__ hi, __nv_bfloat16* __restrict__ lo, int n4)
{
    int i = blockIdx.x * 256 + threadIdx.x;
    if (i >= n4) return;
    float4 v = in[i];
    __nv_bfloat162 h01, h23, l01, l23;
    h01.x = __float2bfloat16(v.x);
    h01.y = __float2bfloat16(v.y);
    h23.x = __float2bfloat16(v.z);
    h23.y = __float2bfloat16(v.w);
    l01.x = __float2bfloat16(v.x - __bfloat162float(h01.x));
    l01.y = __float2bfloat16(v.y - __bfloat162float(h01.y));
    l23.x = __float2bfloat16(v.z - __bfloat162float(h23.x));
    l23.y = __float2bfloat16(v.w - __bfloat162float(h23.y));
    ((__nv_bfloat162*)&hi[4*i])[0] = h01;
    ((__nv_bfloat162*)&hi[4*i])[1] = h23;
    ((__nv_bfloat162*)&lo[4*i])[0] = l01;
    ((__nv_bfloat162*)&lo[4*i])[1] = l23;
}

// ---------------- weight split + transpose: W[K][N] -> Wt[N][K] hi/lo -------
__global__ __launch_bounds__(256) void cvt_wt(
    const float* __restrict__ Wq, const float* __restrict__ Wk,
    const float* __restrict__ Wv, const float* __restrict__ Wu,
    const float* __restrict__ Wo)
{
    __shared__ float ts[64 * 65];
    const int wsel = blockIdx.z;
    const float* W = (wsel == 0) ? Wq : (wsel == 1) ? Wk :
                     (wsel == 2) ? Wv : (wsel == 3) ? Wu : Wo;
    const int k0 = blockIdx.y * 64, n0 = blockIdx.x * 64;

    for (int i = threadIdx.x; i < 4096; i += 256) {
        int r = i >> 6, c = i & 63;
        ts[r * 65 + c] = W[(long)(k0 + r) * Dd + n0 + c];
    }
    __syncthreads();

    const long obase = (long)wsel * Dd * Dd;
    for (int task = threadIdx.x; task < 512; task += 256) {
        int j  = task >> 3;
        int g8 = task & 7;
        __nv_bfloat16 hi8[8], lo8[8];
#pragma unroll
        for (int e = 0; e < 8; e++) {
            float f = ts[(g8 * 8 + e) * 65 + j];
            __nv_bfloat16 h = __float2bfloat16(f);
            hi8[e] = h;
            lo8[e] = __float2bfloat16(f - __bfloat162float(h));
        }
        long o = obase + (long)(n0 + j) * Dd + k0 + g8 * 8;
        *(uint4*)&g_whi[o] = *(uint4*)hi8;
        *(uint4*)&g_wlo[o] = *(uint4*)lo8;
    }
}

// ---------------- GEMM: C[128x128 tile] = A @ Bt^T ---------------------------
#define CHUNKS     16
#define STAGES     3
#define TILE_BYTES 16384          // 128 rows x 128B
#define STAGE_BYTES (4*TILE_BYTES)
#define DYN_SMEM   (STAGES*STAGE_BYTES + 1024)

__device__ __forceinline__ void gemm_tc_body(
    const __nv_bfloat16* __restrict__ Ah, const __nv_bfloat16* __restrict__ Al,
    const __nv_bfloat16* __restrict__ Bh, const __nv_bfloat16* __restrict__ Bl,
    float* __restrict__ C, int brow, int bcol)
{
#if TC_OK
    extern __shared__ __align__(16) char dynsm[];
    __shared__ __align__(8) uint64_t s_mbar[STAGES];
    __shared__ uint32_t s_tmem[1];

    char* tiles_p = (char*)(((uintptr_t)dynsm + 1023) & ~(uintptr_t)1023);
    const uint32_t tiles_u = smem_u32(tiles_p);
    const int tid  = threadIdx.x;
    const int wid  = tid >> 5;
    const int lane = tid & 31;

    if (wid == 0)
        asm volatile("tcgen05.alloc.cta_group::1.sync.aligned.shared::cta.b32 [%0], %1;"
                     :: "r"(smem_u32(s_tmem)), "r"(128u) : "memory");
    if (tid == 0) {
#pragma unroll
        for (int b = 0; b < STAGES; b++)
            asm volatile("mbarrier.init.shared.b64 [%0], %1;"
                         :: "r"(smem_u32(&s_mbar[b])), "r"(1u) : "memory");
    }
    __syncthreads();
    uint32_t tmem;
    asm volatile("ld.shared.b32 %0, [%1];" : "=r"(tmem) : "r"(smem_u32(s_tmem)));

    const uint64_t DESC_BASE =
        (2ull << 61) | (1ull << 46) | (64ull << 32) | (1ull << 16);

    const int l_row = tid >> 1;
    const int l_cb0 = (tid & 1) << 5;
    int ph[STAGES];
#pragma unroll
    for (int b = 0; b < STAGES; b++) ph[b] = 0;

    auto issue_load = [&](int c) {
        const uint32_t pu = tiles_u + (c % STAGES) * STAGE_BYTES;
        const int k0 = c * 64;
        const __nv_bfloat16* s0 = Ah + (long)(brow + l_row) * Dd + k0;
        const __nv_bfloat16* s1 = Al + (long)(brow + l_row) * Dd + k0;
        const __nv_bfloat16* s2 = Bh + (long)(bcol + l_row) * Dd + k0;
        const __nv_bfloat16* s3 = Bl + (long)(bcol + l_row) * Dd + k0;
#pragma unroll
        for (int j = 0; j < 4; j++) {
            int cb = l_cb0 + ((j & 1) << 4) + ((j >> 1) << 6);
            uint32_t so = SWZ(l_row * 128 + cb);
            int ce = cb >> 1;
            cp16(pu + 0 * TILE_BYTES + so, s0 + ce);
            cp16(pu + 1 * TILE_BYTES + so, s1 + ce);
            cp16(pu + 2 * TILE_BYTES + so, s2 + ce);
            cp16(pu + 3 * TILE_BYTES + so, s3 + ce);
        }
        asm volatile("cp.async.commit_group;" ::: "memory");
    };

#pragma unroll
    for (int p = 0; p < STAGES; p++) issue_load(p);

    for (int c = 0; c < CHUNKS; c++) {
        const int buf = c % STAGES;
        asm volatile("cp.async.wait_group %0;" :: "n"(STAGES - 1) : "memory");
        asm volatile("fence.proxy.async.shared::cta;" ::: "memory");
        __syncthreads();

        if (tid == 0) {
            uint32_t tb = tiles_u + buf * STAGE_BYTES;
            uint64_t adh = DESC_BASE | (uint64_t)(((tb + 0 * TILE_BYTES) >> 4) & 0x3FFF);
            uint64_t adl = DESC_BASE | (uint64_t)(((tb + 1 * TILE_BYTES) >> 4) & 0x3FFF);
            uint64_t bdh = DESC_BASE | (uint64_t)(((tb + 2 * TILE_BYTES) >> 4) & 0x3FFF);
            uint64_t bdl = DESC_BASE | (uint64_t)(((tb + 3 * TILE_BYTES) >> 4) & 0x3FFF);
#pragma unroll
            for (int k = 0; k < 4; k++) {
                uint32_t en0 = (c > 0 || k > 0) ? 1u : 0u;
                mma_f16_ss(tmem, adh + 2 * k, bdh + 2 * k, IDESC, en0);
                mma_f16_ss(tmem, adh + 2 * k, bdl + 2 * k, IDESC, 1u);
                mma_f16_ss(tmem, adl + 2 * k, bdh + 2 * k, IDESC, 1u);
            }
            asm volatile(
                "tcgen05.commit.cta_group::1.mbarrier::arrive::one.shared::cluster.b64 [%0];"
                :: "r"(smem_u32(&s_mbar[buf])) : "memory");
        }

        mbar_wait(smem_u32(&s_mbar[buf]), ph[buf]);
        ph[buf] ^= 1;

        if (c + STAGES < CHUNKS)
            issue_load(c + STAGES);
        else
            asm volatile("cp.async.commit_group;" ::: "memory");
    }

    asm volatile("tcgen05.fence::after_thread_sync;" ::: "memory");

    if (wid < 4) {
        int row = brow + wid * 32 + lane;
#pragma unroll
        for (int cb = 0; cb < 4; cb++) {
            uint32_t r[32];
            ldtm32(r, tmem + cb * 32);
            asm volatile("tcgen05.wait::ld.sync.aligned;" ::: "memory");
            float* crow = C + (long)row * Dd + bcol + cb * 32;
#pragma unroll
            for (int e = 0; e < 8; e++)
                *(float4*)(crow + 4 * e) = make_float4(
                    __uint_as_float(r[4*e+0]), __uint_as_float(r[4*e+1]),
                    __uint_as_float(r[4*e+2]), __uint_as_float(r[4*e+3]));
        }
    }
    __syncthreads();
    if (wid == 0)
        asm volatile("tcgen05.dealloc.cta_group::1.sync.aligned.b32 %0, %1;"
                     :: "r"(tmem), "r"(128u));
#else
    // ---------------- SIMT fallback (base-family target) -------------------
    __shared__ __align__(16) float As[8][128];
    __shared__ __align__(16) float Bs[8][128];

    const int tid  = threadIdx.x;
    const int trow = (tid >> 4) << 2;
    const int tcol = (tid & 15) << 2;

    float acc[8][8];
#pragma unroll
    for (int i = 0; i < 8; i++)
#pragma unroll
        for (int j = 0; j < 8; j++) acc[i][j] = 0.f;

    const int  lrow = tid & 127;
    const bool isB  = tid >= 128;
    const __nv_bfloat16* hsrc = isB ? (Bh + (long)(bcol + lrow) * Dd)
                                    : (Ah + (long)(brow + lrow) * Dd);
    const __nv_bfloat16* lsrc = isB ? (Bl + (long)(bcol + lrow) * Dd)
                                    : (Al + (long)(brow + lrow) * Dd);

    for (int k0 = 0; k0 < Dd; k0 += 8) {
        __syncthreads();
        uint4 hraw = *(const uint4*)(hsrc + k0);
        uint4 lraw = *(const uint4*)(lsrc + k0);
        const __nv_bfloat16* h8 = (const __nv_bfloat16*)&hraw;
        const __nv_bfloat16* l8 = (const __nv_bfloat16*)&lraw;
        float (*dst)[128] = isB ? Bs : As;
#pragma unroll
        for (int e = 0; e < 8; e++)
            dst[e][lrow] = __bfloat162float(h8[e]) + __bfloat162float(l8[e]);
        __syncthreads();
#pragma unroll
        for (int kk = 0; kk < 8; kk++) {
            float4 a0 = *(const float4*)&As[kk][trow];
            float4 a1 = *(const float4*)&As[kk][64 + trow];
            float4 b0 = *(const float4*)&Bs[kk][tcol];
            float4 b1 = *(const float4*)&Bs[kk][64 + tcol];
            float ar[8] = {a0.x,a0.y,a0.z,a0.w, a1.x,a1.y,a1.z,a1.w};
            float br[8] = {b0.x,b0.y,b0.z,b0.w, b1.x,b1.y,b1.z,b1.w};
#pragma unroll
            for (int i = 0; i < 8; i++)
#pragma unroll
                for (int j = 0; j < 8; j++) acc[i][j] += ar[i] * br[j];
        }
    }

#pragma unroll
    for (int i = 0; i < 8; i++) {
        int r = brow + ((i < 4) ? (trow + i) : (64 + trow + i - 4));
        float4 c0 = make_float4(acc[i][0], acc[i][1], acc[i][2], acc[i][3]);
        float4 c1 = make_float4(acc[i][4], acc[i][5], acc[i][6], acc[i][7]);
        *(float4*)&C[(long)r * Dd + bcol + tcol]      = c0;
        *(float4*)&C[(long)r * Dd + bcol + 64 + tcol] = c1;
    }
#endif
}

__global__ __launch_bounds__(256) void proj4_tc()
{
    int z = blockIdx.z;
    const __nv_bfloat16* Bh = g_whi + (long)z * Dd * Dd;
    const __nv_bfloat16* Bl = g_wlo + (long)z * Dd * Dd;
    float* Cd = (z == 0) ? g_q : (z == 1) ? g_k : (z == 2) ? g_v : g_u;
    gemm_tc_body(g_xhi, g_xlo, Bh, Bl, Cd, blockIdx.y * 128, blockIdx.x * 128);
}

__global__ __launch_bounds__(256) void gemm_out_tc(float* __restrict__ out)
{
    gemm_tc_body(g_yhi, g_ylo, g_whi + 4l * Dd * Dd, g_wlo + 4l * Dd * Dd,
                 out, blockIdx.y * 128, blockIdx.x * 128);
}

// ---------------- per-segment sums (cp.async double-buffered) ---------------
__global__ __launch_bounds__(256) void seg_sums()
{
    const int bx = blockIdx.x;
    const int s  = bx & (NSEG - 1);
    const int bh = bx >> 3;
    const int b  = bh >> 4;
    const int h  = bh & 15;
    const int tid = threadIdx.x;
    const int d  = tid >> 2;
    const int e0 = (tid & 3) << 4;

    __shared__ __align__(16) float Ks[2][32][64];
    __shared__ __align__(16) float Vs[2][32][64];

    float acc[16];
#pragma unroll
    for (int i = 0; i < 16; i++) acc[i] = 0.f;
    float ctx = 0.f;

    auto issue = [&](int it) {
        int buf = it & 1;
        for (int i = tid; i < 512; i += 256) {
            int tok = i >> 4, c4 = (i & 15) << 2;
            long g = ((long)(b * Tt + s * SEG + it * 32 + tok) * Hh + h) * DhD + c4;
            cp16(smem_u32(&Ks[buf][tok][c4]), &g_k[g]);
            cp16(smem_u32(&Vs[buf][tok][c4]), &g_v[g]);
        }
        asm volatile("cp.async.commit_group;" ::: "memory");
    };

    issue(0);
    for (int it = 0; it < 8; it++) {
        if (it + 1 < 8) issue(it + 1);
        else asm volatile("cp.async.commit_group;" ::: "memory");
        asm volatile("cp.async.wait_group 1;" ::: "memory");
        __syncthreads();
        const int buf = it & 1;
#pragma unroll
        for (int j = 0; j < 32; j++) {
            float kd = Ks[buf][j][d];
            ctx += kd;
            const float4* vr = (const float4*)&Vs[buf][j][e0];
#pragma unroll
            for (int q4 = 0; q4 < 4; q4++) {
                float4 vv = vr[q4];
                acc[4*q4+0] += kd * vv.x;
                acc[4*q4+1] += kd * vv.y;
                acc[4*q4+2] += kd * vv.z;
                acc[4*q4+3] += kd * vv.w;
            }
        }
        __syncthreads();
    }
    long base = ((long)(bh * NSEG + s) * DhD + d) * DhD + e0;
#pragma unroll
    for (int q4 = 0; q4 < 4; q4++)
        *(float4*)&g_Sseg[base + 4*q4] =
            make_float4(acc[4*q4], acc[4*q4+1], acc[4*q4+2], acc[4*q4+3]);
    if ((tid & 3) == 0) g_cctx[(bh * NSEG + s) * DhD + d] = ctx;
}

// ---------------- prefix over segments --------------------------------------
__global__ __launch_bounds__(256) void seg_prefix()
{
    const int bh = blockIdx.x;
    for (int i = threadIdx.x; i < DhD * DhD; i += 256) {
        float run = 0.f;
#pragma unroll
        for (int s = 0; s < NSEG; s++) {
            long idx = ((long)(bh * NSEG + s)) * (DhD * DhD) + i;
            run += g_Sseg[idx];
            g_cS[idx] = run;
        }
    }
}

// ---------------- attention/mixing: 512 threads, e-split halves -------------
struct AttnSm {
    float Ks[64][64];     // 16KB (k / cS tiles)
    float Vs[64][64];     // 16KB
    float Cs[8][64];      // 2KB
    float Wsm[8][256];    // 8KB
    float Wcur[256];      // 1KB
    float Part[256][10];  // 10KB (eh=1 score partials)
};
#define ATTN_SMEM ((int)sizeof(AttnSm))

__global__ __launch_bounds__(512) void attn_kernel()
{
    extern __shared__ __align__(16) char attn_raw[];
    AttnSm* S = (AttnSm*)attn_raw;

    const int bx  = blockIdx.x;
    const int seg = bx & (NSEG - 1);
    const int bh  = bx >> 3;
    const int b   = bh >> 4;
    const int h   = bh & 15;
    const int tid = threadIdx.x;
    const int t   = tid & 255;        // token in segment
    const int eh  = tid >> 8;         // 0/1: output e-half
    const int e0  = eh << 5;          // 0 or 32
    const int cur = seg;

    const long rowbase = ((long)(b * Tt + seg * SEG + t) * Hh + h) * DhD;

    // ---------- phase 1: scores (split by d-half across the thread pair) ----
    float u32r[32];
    {
        const float4* up = (const float4*)&g_u[rowbase + e0];
#pragma unroll
        for (int i = 0; i < 8; i++) {
            float4 w = up[i];
            u32r[4*i] = w.x; u32r[4*i+1] = w.y; u32r[4*i+2] = w.z; u32r[4*i+3] = w.w;
        }
    }
    for (int i = tid; i < cur * 64; i += 512)
        S->Cs[i >> 6][i & 63] = g_cctx[(bh * NSEG + (i >> 6)) * DhD + (i & 63)];
    __syncthreads();

    float sc[8];
    float ons = 0.f;
#pragma unroll
    for (int s = 0; s < 8; s++) {
        float a = 0.f;
        if (s < cur) {
#pragma unroll
            for (int j = 0; j < 32; j++) a += u32r[j] * S->Cs[s][e0 + j];
        }
        sc[s] = a;
    }
    for (int tile = 0; tile < 4; tile++) {
        __syncthreads();
        for (int i = tid; i < 1024; i += 512) {
            int tok = i >> 4, c4 = (i & 15) << 2;
            long g = ((long)(b * Tt + seg * SEG + tile * 64 + tok) * Hh + h) * DhD + c4;
            *(float4*)&S->Ks[tok][c4] = *(const float4*)&g_k[g];
        }
        __syncthreads();
        int lim = t - tile * 64;
        if (lim >= 0) {
            int n = lim < 63 ? lim : 63;
            for (int tp = 0; tp <= n; tp++) {
                const float* kr = &S->Ks[tp][e0];
                float a = 0.f;
#pragma unroll
                for (int j = 0; j < 32; j++) a += u32r[j] * kr[j];
                ons += a;
            }
        }
    }
    if (eh == 1) {
#pragma unroll
        for (int s = 0; s < 8; s++) S->Part[t][s] = sc[s];
        S->Part[t][8] = ons;
    }
    __syncthreads();
    if (eh == 0) {
#pragma unroll
        for (int s = 0; s < 8; s++) sc[s] += S->Part[t][s];
        ons += S->Part[t][8];
        float wcur;
        if (cur == 0) {
            wcur = 1.f;
        } else {
            float m = ons;
#pragma unroll
            for (int s = 0; s < 8; s++) if (s < cur && sc[s] > m) m = sc[s];
            float eon = expf(ons - m);
            float denom = eon;
#pragma unroll
            for (int s = 0; s < 8; s++) {
                if (s < cur) { float e = expf(sc[s] - m); sc[s] = e; denom += e; }
            }
            float inv = 1.f / denom;
            wcur = eon * inv;
#pragma unroll
            for (int s = 0; s < 8; s++)
                if (s < cur) S->Wsm[s][t] = sc[s] * inv + ((s == cur - 1) ? wcur : 0.f);
        }
        S->Wcur[t] = wcur;
    }
    __syncthreads();

    // ---------- phase 2: outputs (each thread: 32 of the 64 e-dims) ---------
    float4 q4r[16];
    {
        const float4* qp = (const float4*)&g_q[rowbase];
#pragma unroll
        for (int i = 0; i < 16; i++) q4r[i] = qp[i];
    }
    float outr[32];
#pragma unroll
    for (int i = 0; i < 32; i++) outr[i] = 0.f;

    for (int s = 0; s < cur; s++) {
        __syncthreads();
        for (int i = tid; i < 1024; i += 512) {
            int dd = i >> 4, c4 = (i & 15) << 2;
            *(float4*)&S->Ks[dd][c4] =
                *(const float4*)&g_cS[((long)(bh * NSEG + s)) * (DhD*DhD) + dd * 64 + c4];
        }
        __syncthreads();
        float ws = S->Wsm[s][t];
#pragma unroll
        for (int d4 = 0; d4 < 16; d4++) {
            float4 qv = q4r[d4];
            float fq[4] = {ws*qv.x, ws*qv.y, ws*qv.z, ws*qv.w};
#pragma unroll
            for (int c = 0; c < 4; c++) {
                float f = fq[c];
                const float4* sr = (const float4*)&S->Ks[4*d4 + c][e0];
#pragma unroll
                for (int e = 0; e < 8; e++) {
                    float4 s4 = sr[e];
                    outr[4*e+0] += f * s4.x;
                    outr[4*e+1] += f * s4.y;
                    outr[4*e+2] += f * s4.z;
                    outr[4*e+3] += f * s4.w;
                }
            }
        }
    }

    const float wc = S->Wcur[t];
    for (int tile = 0; tile < 4; tile++) {
        __syncthreads();
        for (int i = tid; i < 1024; i += 512) {
            int tok = i >> 4, c4 = (i & 15) << 2;
            long g = ((long)(b * Tt + seg * SEG + tile * 64 + tok) * Hh + h) * DhD + c4;
            *(float4*)&S->Ks[tok][c4] = *(const float4*)&g_k[g];
            *(float4*)&S->Vs[tok][c4] = *(const float4*)&g_v[g];
        }
        __syncthreads();
        int lim = t - tile * 64;
        if (lim >= 0) {
            int n = lim < 63 ? lim : 63;
            for (int tp = 0; tp <= n; tp++) {
                const float4* kr = (const float4*)S->Ks[tp];
                float a = 0.f;
#pragma unroll
                for (int j = 0; j < 16; j++) {
                    float4 k4 = kr[j];
                    a += q4r[j].x*k4.x + q4r[j].y*k4.y + q4r[j].z*k4.z + q4r[j].w*k4.w;
                }
                float f = wc * a;
                const float4* vr = (const float4*)&S->Vs[tp][e0];
#pragma unroll
                for (int e = 0; e < 8; e++) {
                    float4 v4 = vr[e];
                    outr[4*e+0] += f * v4.x;
                    outr[4*e+1] += f * v4.y;
                    outr[4*e+2] += f * v4.z;
                    outr[4*e+3] += f * v4.w;
                }
            }
        }
    }

    float4* yp = (float4*)&g_y[rowbase + e0];
#pragma unroll
    for (int e = 0; e < 8; e++)
        yp[e] = make_float4(outr[4*e], outr[4*e+1], outr[4*e+2], outr[4*e+3]);
}

// ---------------- launch ----------------------------------------------------
extern "C" void kernel_launch(void* const* d_in, const int* in_sizes, int n_in,
                              void* d_out, int out_size)
{
    const float* x  = (const float*)d_in[0];
    const float* Wq = (const float*)d_in[1];
    const float* Wk = (const float*)d_in[2];
    const float* Wv = (const float*)d_in[3];
    const float* Wu = (const float*)d_in[4];
    const float* Wo = (const float*)d_in[5];
    float* out = (float*)d_out;

    __nv_bfloat16 *pxh, *pxl, *pyh, *pyl;
    float* pyf;
    cudaGetSymbolAddress((void**)&pxh, g_xhi);
    cudaGetSymbolAddress((void**)&pxl, g_xlo);
    cudaGetSymbolAddress((void**)&pyh, g_yhi);
    cudaGetSymbolAddress((void**)&pyl, g_ylo);
    cudaGetSymbolAddress((void**)&pyf, g_y);

    cudaFuncSetAttribute(proj4_tc,    cudaFuncAttributeMaxDynamicSharedMemorySize, DYN_SMEM);
    cudaFuncSetAttribute(gemm_out_tc, cudaFuncAttributeMaxDynamicSharedMemorySize, DYN_SMEM);
    cudaFuncSetAttribute(attn_kernel, cudaFuncAttributeMaxDynamicSharedMemorySize, ATTN_SMEM);

    const int N4 = BT * Dd / 4;
    cvt_split<<<N4 / 256, 256>>>((const float4*)x, pxh, pxl, N4);

    dim3 gw(16, 16, 5);
    cvt_wt<<<gw, 256>>>(Wq, Wk, Wv, Wu, Wo);

    dim3 gp(Dd / 128, BT / 128, 4);                // (8, 64, 4)
    proj4_tc<<<gp, 256, DYN_SMEM>>>();

    seg_sums  <<<BH * NSEG, 256>>>();
    seg_prefix<<<BH,        256>>>();
    attn_kernel<<<BH * NSEG, 512, ATTN_SMEM>>>();

    cvt_split<<<N4 / 256, 256>>>((const float4*)pyf, pyh, pyl, N4);

    dim3 gg(Dd / 128, BT / 128);                   // (8, 64)
    gemm_out_tc<<<gg, 256, DYN_SMEM>>>(out);
}

// round 16
// speedup vs baseline: 1.0479x; 1.0479x over previous
#include <cuda_runtime.h>
#include <cuda_bf16.h>
#include <math.h>
#include <stdint.h>

#define Bb   4
#define Tt   2048
#define Dd   1024
#define Hh   16
#define DhD  64
#define SEG  256
#define NSEG 8
#define BT   (Bb*Tt)      // 8192
#define BH   (Bb*Hh)      // 64

#define SWZ(o) ((o) ^ ((((o) >> 3)) & 0x70))

// idesc kind::f16 cg1: F32 accum, BF16 a/b
#define IDESC     0x8200490u   // M=128, N=128
#define IDESC_N64 0x8100490u   // M=128, N=64

// tcgen05 is only available on arch-SPECIFIC targets (sm_103a / sm_100a).
#if defined(__CUDA_ARCH_FEAT_SM103_ALL) || defined(__CUDA_ARCH_FEAT_SM100_ALL) || defined(__CUDA_ARCH_SPECIFIC__)
#define TC_OK 1
#else
#define TC_OK 0
#endif

// ---------------- scratch (device globals; no allocations allowed) ----------
__device__ __align__(16) float g_q[BT*Dd];
__device__ __align__(16) float g_k[BT*Dd];
__device__ __align__(16) float g_v[BT*Dd];
__device__ __align__(16) float g_u[BT*Dd];
__device__ __align__(16) float g_y[BT*Dd];
__device__ __align__(16) float g_Sseg[BH*NSEG*DhD*DhD];
__device__ __align__(16) float g_cctx[BH*NSEG*DhD];

// bf16 split operands (weights stored TRANSPOSED: [N][K] K-major)
__device__ __align__(16) __nv_bfloat16 g_xhi[BT*Dd];
__device__ __align__(16) __nv_bfloat16 g_xlo[BT*Dd];
__device__ __align__(16) __nv_bfloat16 g_yhi[BT*Dd];
__device__ __align__(16) __nv_bfloat16 g_ylo[BT*Dd];
__device__ __align__(16) __nv_bfloat16 g_qhi[BT*Dd];
__device__ __align__(16) __nv_bfloat16 g_qlo[BT*Dd];
__device__ __align__(16) __nv_bfloat16 g_whi[5*Dd*Dd];
__device__ __align__(16) __nv_bfloat16 g_wlo[5*Dd*Dd];

// cached-prefix matrices, transposed ([s][e][d], K-major), bf16 hi/lo. s=0..6.
__device__ __align__(16) __nv_bfloat16 g_cSthi[BH*7*DhD*DhD];
__device__ __align__(16) __nv_bfloat16 g_cStlo[BH*7*DhD*DhD];
// R[bh][s][tok][e] = q_tok @ cS[s]   (valid for tok in segments > s)
__device__ __align__(16) float g_R[(long)BH*7*Tt*DhD];

// ---------------- small helpers ---------------------------------------------
__device__ __forceinline__ uint32_t smem_u32(const void* p) {
    uint32_t a;
    asm("{ .reg .u64 t; cvta.to.shared.u64 t, %1; cvt.u32.u64 %0, t; }"
        : "=r"(a) : "l"(p));
    return a;
}

__device__ __forceinline__ void cp16(uint32_t saddr, const void* gptr) {
    asm volatile("cp.async.cg.shared.global [%0], [%1], 16;"
                 :: "r"(saddr), "l"(gptr));
}

#if TC_OK
__device__ __forceinline__ void mma_f16_ss(uint32_t d, uint64_t ad, uint64_t bd,
                                           uint32_t idesc, uint32_t en) {
    asm volatile(
        "{\n\t.reg .pred p;\n\tsetp.ne.u32 p, %5, 0;\n\t"
        "tcgen05.mma.cta_group::1.kind::f16 [%0], %1, %2, %3, {%4,%4,%4,%4}, p;\n\t}"
        :: "r"(d), "l"(ad), "l"(bd), "r"(idesc), "r"(0u), "r"(en) : "memory");
}

__device__ __forceinline__ void mbar_wait(uint32_t mbar, int parity) {
    asm volatile(
        "{\n\t.reg .pred P;\n\t"
        "LAB_%=:\n\t"
        "mbarrier.try_wait.parity.acquire.cta.shared::cta.b64 P, [%0], %1;\n\t"
        "@!P bra LAB_%=;\n\t}"
        :: "r"(mbar), "r"(parity) : "memory");
}

__device__ __forceinline__ void ldtm32(uint32_t* r, uint32_t addr) {
    asm volatile(
        "tcgen05.ld.sync.aligned.32x32b.x32.b32 "
        "{%0, %1, %2, %3, %4, %5, %6, %7, "
        " %8, %9, %10, %11, %12, %13, %14, %15, "
        " %16, %17, %18, %19, %20, %21, %22, %23, "
        " %24, %25, %26, %27, %28, %29, %30, %31}, [%32];"
        : "=r"(r[0]),  "=r"(r[1]),  "=r"(r[2]),  "=r"(r[3]),
          "=r"(r[4]),  "=r"(r[5]),  "=r"(r[6]),  "=r"(r[7]),
          "=r"(r[8]),  "=r"(r[9]),  "=r"(r[10]), "=r"(r[11]),
          "=r"(r[12]), "=r"(r[13]), "=r"(r[14]), "=r"(r[15]),
          "=r"(r[16]), "=r"(r[17]), "=r"(r[18]), "=r"(r[19]),
          "=r"(r[20]), "=r"(r[21]), "=r"(r[22]), "=r"(r[23]),
          "=r"(r[24]), "=r"(r[25]), "=r"(r[26]), "=r"(r[27]),
          "=r"(r[28]), "=r"(r[29]), "=r"(r[30]), "=r"(r[31])
        : "r"(addr));
}
#endif

// ---------------- fp32 -> (bf16 hi, bf16 lo) split ---------------------------
__global__ __launch_bounds__(256) void cvt_split(
    const float4* __restrict__ in,
    __nv_bfloat16* __restrict__ hi, __nv_bfloat16* __restrict__ lo, int n4)
{
    int i = blockIdx.x * 256 + threadIdx.x;
    if (i >= n4) return;
    float4 v = in[i];
    __nv_bfloat162 h01, h23, l01, l23;
    h01.x = __float2bfloat16(v.x);
    h01.y = __float2bfloat16(v.y);
    h23.x = __float2bfloat16(v.z);
    h23.y = __float2bfloat16(v.w);
    l01.x = __float2bfloat16(v.x - __bfloat162float(h01.x));
    l01.y = __float2bfloat16(v.y - __bfloat162float(h01.y));
    l23.x = __float2bfloat16(v.z - __bfloat162float(h23.x));
    l23.y = __float2bfloat16(v.w - __bfloat162float(h23.y));
    ((__nv_bfloat162*)&hi[4*i])[0] = h01;
    ((__nv_bfloat162*)&hi[4*i])[1] = h23;
    ((__nv_bfloat162*)&lo[4*i])[0] = l01;
    ((__nv_bfloat162*)&lo[4*i])[1] = l23;
}

// ---------------- weight split + transpose: W[K][N] -> Wt[N][K] hi/lo -------
__global__ __launch_bounds__(256) void cvt_wt(
    const float* __restrict__ Wq, const float* __restrict__ Wk,
    const float* __restrict__ Wv, const float* __restrict__ Wu,
    const float* __restrict__ Wo)
{
    __shared__ float ts[64 * 65];
    const int wsel = blockIdx.z;
    const float* W = (wsel == 0) ? Wq : (wsel == 1) ? Wk :
                     (wsel == 2) ? Wv : (wsel == 3) ? Wu : Wo;
    const int k0 = blockIdx.y * 64, n0 = blockIdx.x * 64;

    for (int i = threadIdx.x; i < 4096; i += 256) {
        int r = i >> 6, c = i & 63;
        ts[r * 65 + c] = W[(long)(k0 + r) * Dd + n0 + c];
    }
    __syncthreads();

    const long obase = (long)wsel * Dd * Dd;
    for (int task = threadIdx.x; task < 512; task += 256) {
        int j  = task >> 3;
        int g8 = task & 7;
        __nv_bfloat16 hi8[8], lo8[8];
#pragma unroll
        for (int e = 0; e < 8; e++) {
            float f = ts[(g8 * 8 + e) * 65 + j];
            __nv_bfloat16 h = __float2bfloat16(f);
            hi8[e] = h;
            lo8[e] = __float2bfloat16(f - __bfloat162float(h));
        }
        long o = obase + (long)(n0 + j) * Dd + k0 + g8 * 8;
        *(uint4*)&g_whi[o] = *(uint4*)hi8;
        *(uint4*)&g_wlo[o] = *(uint4*)lo8;
    }
}

// ---------------- GEMM: C[128x128 tile] = A @ Bt^T ---------------------------
#define CHUNKS     16
#define STAGES     3
#define TILE_BYTES 16384          // 128 rows x 128B
#define STAGE_BYTES (4*TILE_BYTES)
#define DYN_SMEM   (STAGES*STAGE_BYTES + 1024)

__device__ __forceinline__ void gemm_tc_body(
    const __nv_bfloat16* __restrict__ Ah, const __nv_bfloat16* __restrict__ Al,
    const __nv_bfloat16* __restrict__ Bh, const __nv_bfloat16* __restrict__ Bl,
    float* __restrict__ C, int brow, int bcol)
{
#if TC_OK
    extern __shared__ __align__(16) char dynsm[];
    __shared__ __align__(8) uint64_t s_mbar[STAGES];
    __shared__ uint32_t s_tmem[1];

    char* tiles_p = (char*)(((uintptr_t)dynsm + 1023) & ~(uintptr_t)1023);
    const uint32_t tiles_u = smem_u32(tiles_p);
    const int tid  = threadIdx.x;
    const int wid  = tid >> 5;
    const int lane = tid & 31;

    if (wid == 0)
        asm volatile("tcgen05.alloc.cta_group::1.sync.aligned.shared::cta.b32 [%0], %1;"
                     :: "r"(smem_u32(s_tmem)), "r"(128u) : "memory");
    if (tid == 0) {
#pragma unroll
        for (int b = 0; b < STAGES; b++)
            asm volatile("mbarrier.init.shared.b64 [%0], %1;"
                         :: "r"(smem_u32(&s_mbar[b])), "r"(1u) : "memory");
    }
    __syncthreads();
    uint32_t tmem;
    asm volatile("ld.shared.b32 %0, [%1];" : "=r"(tmem) : "r"(smem_u32(s_tmem)));

    const uint64_t DESC_BASE =
        (2ull << 61) | (1ull << 46) | (64ull << 32) | (1ull << 16);

    const int l_row = tid >> 1;
    const int l_cb0 = (tid & 1) << 5;
    int ph[STAGES];
#pragma unroll
    for (int b = 0; b < STAGES; b++) ph[b] = 0;

    auto issue_load = [&](int c) {
        const uint32_t pu = tiles_u + (c % STAGES) * STAGE_BYTES;
        const int k0 = c * 64;
        const __nv_bfloat16* s0 = Ah + (long)(brow + l_row) * Dd + k0;
        const __nv_bfloat16* s1 = Al + (long)(brow + l_row) * Dd + k0;
        const __nv_bfloat16* s2 = Bh + (long)(bcol + l_row) * Dd + k0;
        const __nv_bfloat16* s3 = Bl + (long)(bcol + l_row) * Dd + k0;
#pragma unroll
        for (int j = 0; j < 4; j++) {
            int cb = l_cb0 + ((j & 1) << 4) + ((j >> 1) << 6);
            uint32_t so = SWZ(l_row * 128 + cb);
            int ce = cb >> 1;
            cp16(pu + 0 * TILE_BYTES + so, s0 + ce);
            cp16(pu + 1 * TILE_BYTES + so, s1 + ce);
            cp16(pu + 2 * TILE_BYTES + so, s2 + ce);
            cp16(pu + 3 * TILE_BYTES + so, s3 + ce);
        }
        asm volatile("cp.async.commit_group;" ::: "memory");
    };

#pragma unroll
    for (int p = 0; p < STAGES; p++) issue_load(p);

    for (int c = 0; c < CHUNKS; c++) {
        const int buf = c % STAGES;
        asm volatile("cp.async.wait_group %0;" :: "n"(STAGES - 1) : "memory");
        asm volatile("fence.proxy.async.shared::cta;" ::: "memory");
        __syncthreads();

        if (tid == 0) {
            uint32_t tb = tiles_u + buf * STAGE_BYTES;
            uint64_t adh = DESC_BASE | (uint64_t)(((tb + 0 * TILE_BYTES) >> 4) & 0x3FFF);
            uint64_t adl = DESC_BASE | (uint64_t)(((tb + 1 * TILE_BYTES) >> 4) & 0x3FFF);
            uint64_t bdh = DESC_BASE | (uint64_t)(((tb + 2 * TILE_BYTES) >> 4) & 0x3FFF);
            uint64_t bdl = DESC_BASE | (uint64_t)(((tb + 3 * TILE_BYTES) >> 4) & 0x3FFF);
#pragma unroll
            for (int k = 0; k < 4; k++) {
                uint32_t en0 = (c > 0 || k > 0) ? 1u : 0u;
                mma_f16_ss(tmem, adh + 2 * k, bdh + 2 * k, IDESC, en0);
                mma_f16_ss(tmem, adh + 2 * k, bdl + 2 * k, IDESC, 1u);
                mma_f16_ss(tmem, adl + 2 * k, bdh + 2 * k, IDESC, 1u);
            }
            asm volatile(
                "tcgen05.commit.cta_group::1.mbarrier::arrive::one.shared::cluster.b64 [%0];"
                :: "r"(smem_u32(&s_mbar[buf])) : "memory");
        }

        mbar_wait(smem_u32(&s_mbar[buf]), ph[buf]);
        ph[buf] ^= 1;

        if (c + STAGES < CHUNKS)
            issue_load(c + STAGES);
        else
            asm volatile("cp.async.commit_group;" ::: "memory");
    }

    asm volatile("tcgen05.fence::after_thread_sync;" ::: "memory");

    if (wid < 4) {
        int row = brow + wid * 32 + lane;
#pragma unroll
        for (int cb = 0; cb < 4; cb++) {
            uint32_t r[32];
            ldtm32(r, tmem + cb * 32);
            asm volatile("tcgen05.wait::ld.sync.aligned;" ::: "memory");
            float* crow = C + (long)row * Dd + bcol + cb * 32;
#pragma unroll
            for (int e = 0; e < 8; e++)
                *(float4*)(crow + 4 * e) = make_float4(
                    __uint_as_float(r[4*e+0]), __uint_as_float(r[4*e+1]),
                    __uint_as_float(r[4*e+2]), __uint_as_float(r[4*e+3]));
        }
    }
    __syncthreads();
    if (wid == 0)
        asm volatile("tcgen05.dealloc.cta_group::1.sync.aligned.b32 %0, %1;"
                     :: "r"(tmem), "r"(128u));
#else
    // ---------------- SIMT fallback (base-family target) -------------------
    __shared__ __align__(16) float As[8][128];
    __shared__ __align__(16) float Bs[8][128];

    const int tid  = threadIdx.x;
    const int trow = (tid >> 4) << 2;
    const int tcol = (tid & 15) << 2;

    float acc[8][8];
#pragma unroll
    for (int i = 0; i < 8; i++)
#pragma unroll
        for (int j = 0; j < 8; j++) acc[i][j] = 0.f;

    const int  lrow = tid & 127;
    const bool isB  = tid >= 128;
    const __nv_bfloat16* hsrc = isB ? (Bh + (long)(bcol + lrow) * Dd)
                                    : (Ah + (long)(brow + lrow) * Dd);
    const __nv_bfloat16* lsrc = isB ? (Bl + (long)(bcol + lrow) * Dd)
                                    : (Al + (long)(brow + lrow) * Dd);

    for (int k0 = 0; k0 < Dd; k0 += 8) {
        __syncthreads();
        uint4 hraw = *(const uint4*)(hsrc + k0);
        uint4 lraw = *(const uint4*)(lsrc + k0);
        const __nv_bfloat16* h8 = (const __nv_bfloat16*)&hraw;
        const __nv_bfloat16* l8 = (const __nv_bfloat16*)&lraw;
        float (*dst)[128] = isB ? Bs : As;
#pragma unroll
        for (int e = 0; e < 8; e++)
            dst[e][lrow] = __bfloat162float(h8[e]) + __bfloat162float(l8[e]);
        __syncthreads();
#pragma unroll
        for (int kk = 0; kk < 8; kk++) {
            float4 a0 = *(const float4*)&As[kk][trow];
            float4 a1 = *(const float4*)&As[kk][64 + trow];
            float4 b0 = *(const float4*)&Bs[kk][tcol];
            float4 b1 = *(const float4*)&Bs[kk][64 + tcol];
            float ar[8] = {a0.x,a0.y,a0.z,a0.w, a1.x,a1.y,a1.z,a1.w};
            float br[8] = {b0.x,b0.y,b0.z,b0.w, b1.x,b1.y,b1.z,b1.w};
#pragma unroll
            for (int i = 0; i < 8; i++)
#pragma unroll
                for (int j = 0; j < 8; j++) acc[i][j] += ar[i] * br[j];
        }
    }

#pragma unroll
    for (int i = 0; i < 8; i++) {
        int r = brow + ((i < 4) ? (trow + i) : (64 + trow + i - 4));
        float4 c0 = make_float4(acc[i][0], acc[i][1], acc[i][2], acc[i][3]);
        float4 c1 = make_float4(acc[i][4], acc[i][5], acc[i][6], acc[i][7]);
        *(float4*)&C[(long)r * Dd + bcol + tcol]      = c0;
        *(float4*)&C[(long)r * Dd + bcol + 64 + tcol] = c1;
    }
#endif
}

__global__ __launch_bounds__(256) void proj4_tc()
{
    int z = blockIdx.z;
    const __nv_bfloat16* Bh = g_whi + (long)z * Dd * Dd;
    const __nv_bfloat16* Bl = g_wlo + (long)z * Dd * Dd;
    float* Cd = (z == 0) ? g_q : (z == 1) ? g_k : (z == 2) ? g_v : g_u;
    gemm_tc_body(g_xhi, g_xlo, Bh, Bl, Cd, blockIdx.y * 128, blockIdx.x * 128);
}

__global__ __launch_bounds__(256) void gemm_out_tc(float* __restrict__ out)
{
    gemm_tc_body(g_yhi, g_ylo, g_whi + 4l * Dd * Dd, g_wlo + 4l * Dd * Dd,
                 out, blockIdx.y * 128, blockIdx.x * 128);
}

// ---------------- per-segment sums (cp.async double-buffered) ---------------
__global__ __launch_bounds__(256) void seg_sums()
{
    const int bx = blockIdx.x;
    const int s  = bx & (NSEG - 1);
    const int bh = bx >> 3;
    const int b  = bh >> 4;
    const int h  = bh & 15;
    const int tid = threadIdx.x;
    const int d  = tid >> 2;
    const int e0 = (tid & 3) << 4;

    __shared__ __align__(16) float Ks[2][32][64];
    __shared__ __align__(16) float Vs[2][32][64];

    float acc[16];
#pragma unroll
    for (int i = 0; i < 16; i++) acc[i] = 0.f;
    float ctx = 0.f;

    auto issue = [&](int it) {
        int buf = it & 1;
        for (int i = tid; i < 512; i += 256) {
            int tok = i >> 4, c4 = (i & 15) << 2;
            long g = ((long)(b * Tt + s * SEG + it * 32 + tok) * Hh + h) * DhD + c4;
            cp16(smem_u32(&Ks[buf][tok][c4]), &g_k[g]);
            cp16(smem_u32(&Vs[buf][tok][c4]), &g_v[g]);
        }
        asm volatile("cp.async.commit_group;" ::: "memory");
    };

    issue(0);
    for (int it = 0; it < 8; it++) {
        if (it + 1 < 8) issue(it + 1);
        else asm volatile("cp.async.commit_group;" ::: "memory");
        asm volatile("cp.async.wait_group 1;" ::: "memory");
        __syncthreads();
        const int buf = it & 1;
#pragma unroll
        for (int j = 0; j < 32; j++) {
            float kd = Ks[buf][j][d];
            ctx += kd;
            const float4* vr = (const float4*)&Vs[buf][j][e0];
#pragma unroll
            for (int q4 = 0; q4 < 4; q4++) {
                float4 vv = vr[q4];
                acc[4*q4+0] += kd * vv.x;
                acc[4*q4+1] += kd * vv.y;
                acc[4*q4+2] += kd * vv.z;
                acc[4*q4+3] += kd * vv.w;
            }
        }
        __syncthreads();
    }
    long base = ((long)(bh * NSEG + s) * DhD + d) * DhD + e0;
#pragma unroll
    for (int q4 = 0; q4 < 4; q4++)
        *(float4*)&g_Sseg[base + 4*q4] =
            make_float4(acc[4*q4], acc[4*q4+1], acc[4*q4+2], acc[4*q4+3]);
    if ((tid & 3) == 0) g_cctx[(bh * NSEG + s) * DhD + d] = ctx;
}

// ---------------- prefix over segments -> transposed bf16 hi/lo -------------
// cSt[s][e][d] = sum_{s'<=s} Sseg[s'][d][e],  s = 0..6 only (s=7 never read)
__global__ __launch_bounds__(256) void seg_prefix()
{
    __shared__ float run[64 * 65];
    const int bh = blockIdx.x;

    for (int i = threadIdx.x; i < 4096; i += 256)
        run[(i >> 6) * 65 + (i & 63)] = 0.f;
    __syncthreads();

    for (int s = 0; s < 7; s++) {
        for (int i = threadIdx.x; i < 4096; i += 256)
            run[(i >> 6) * 65 + (i & 63)] +=
                g_Sseg[((long)(bh * NSEG + s)) * 4096 + i];
        __syncthreads();
        for (int j = threadIdx.x; j < 4096; j += 256) {
            int d = j & 63, e = j >> 6;
            float v = run[d * 65 + e];
            __nv_bfloat16 hh = __float2bfloat16(v);
            long o = ((long)((bh * 7 + s) * DhD + e)) * DhD + d;
            g_cSthi[o] = hh;
            g_cStlo[o] = __float2bfloat16(v - __bfloat162float(hh));
        }
        __syncthreads();
    }
}

// ---------------- R GEMM: R[bh][s][tok] = q_tok @ cS[s] ----------------------
// grid (mt=14, s=7, bh=64); tile M=128 tokens, N=64, K=64 (single chunk).
#define AR_TILE_A 16384       // 128 rows x 128B
#define AR_TILE_B 8192        // 64 rows x 128B
#define AR_SMEM   (2*AR_TILE_A + 2*AR_TILE_B + 1024)

__global__ __launch_bounds__(256) void attn_R_kernel()
{
    const int mt = blockIdx.x, s = blockIdx.y, bh = blockIdx.z;
    const int row0 = ((s + 1) * 2 + mt) * 128;
    if (row0 >= Tt) return;
    const int b = bh >> 4, h = bh & 15;

#if TC_OK
    extern __shared__ __align__(16) char dynsm[];
    __shared__ __align__(8) uint64_t s_mbar;
    __shared__ uint32_t s_tmem[1];

    char* tp = (char*)(((uintptr_t)dynsm + 1023) & ~(uintptr_t)1023);
    const uint32_t tu = smem_u32(tp);
    const int tid  = threadIdx.x;
    const int wid  = tid >> 5;
    const int lane = tid & 31;

    if (wid == 0)
        asm volatile("tcgen05.alloc.cta_group::1.sync.aligned.shared::cta.b32 [%0], %1;"
                     :: "r"(smem_u32(s_tmem)), "r"(128u) : "memory");
    if (tid == 0)
        asm volatile("mbarrier.init.shared.b64 [%0], %1;"
                     :: "r"(smem_u32(&s_mbar)), "r"(1u) : "memory");
    __syncthreads();
    uint32_t tmem;
    asm volatile("ld.shared.b32 %0, [%1];" : "=r"(tmem) : "r"(smem_u32(s_tmem)));

    const uint64_t DESC_BASE =
        (2ull << 61) | (1ull << 46) | (64ull << 32) | (1ull << 16);

    // A: q rows [row0..row0+127], 128B/row (64 bf16)
    for (int i = tid; i < 1024; i += 256) {
        int row = i >> 3, cb = (i & 7) << 4;
        uint32_t so = SWZ(row * 128 + cb);
        long ga = ((long)(b * Tt + row0 + row) * Hh + h) * DhD + (cb >> 1);
        cp16(tu + so, g_qhi + ga);
        cp16(tu + AR_TILE_A + so, g_qlo + ga);
    }
    // B: cSt[s] 64 rows x 128B
    for (int i = tid; i < 512; i += 256) {
        int row = i >> 3, cb = (i & 7) << 4;
        uint32_t so = SWZ(row * 128 + cb);
        long gb = ((long)((bh * 7 + s) * DhD + row)) * DhD + (cb >> 1);
        cp16(tu + 2 * AR_TILE_A + so, g_cSthi + gb);
        cp16(tu + 2 * AR_TILE_A + AR_TILE_B + so, g_cStlo + gb);
    }
    asm volatile("cp.async.commit_group;" ::: "memory");
    asm volatile("cp.async.wait_group 0;" ::: "memory");
    asm volatile("fence.proxy.async.shared::cta;" ::: "memory");
    __syncthreads();

    if (tid == 0) {
        uint64_t adh = DESC_BASE | (uint64_t)((tu >> 4) & 0x3FFF);
        uint64_t adl = DESC_BASE | (uint64_t)(((tu + AR_TILE_A) >> 4) & 0x3FFF);
        uint64_t bdh = DESC_BASE | (uint64_t)(((tu + 2 * AR_TILE_A) >> 4) & 0x3FFF);
        uint64_t bdl = DESC_BASE | (uint64_t)(((tu + 2 * AR_TILE_A + AR_TILE_B) >> 4) & 0x3FFF);
#pragma unroll
        for (int k = 0; k < 4; k++) {
            mma_f16_ss(tmem, adh + 2 * k, bdh + 2 * k, IDESC_N64, (k > 0) ? 1u : 0u);
            mma_f16_ss(tmem, adh + 2 * k, bdl + 2 * k, IDESC_N64, 1u);
            mma_f16_ss(tmem, adl + 2 * k, bdh + 2 * k, IDESC_N64, 1u);
        }
        asm volatile(
            "tcgen05.commit.cta_group::1.mbarrier::arrive::one.shared::cluster.b64 [%0];"
            :: "r"(smem_u32(&s_mbar)) : "memory");
    }
    mbar_wait(smem_u32(&s_mbar), 0);
    asm volatile("tcgen05.fence::after_thread_sync;" ::: "memory");

    if (wid < 4) {
        int tok = row0 + wid * 32 + lane;
        float* crow = g_R + ((long)((bh * 7 + s) * Tt + tok)) * DhD;
#pragma unroll
        for (int cb = 0; cb < 2; cb++) {
            uint32_t r[32];
            ldtm32(r, tmem + cb * 32);
            asm volatile("tcgen05.wait::ld.sync.aligned;" ::: "memory");
#pragma unroll
            for (int e = 0; e < 8; e++)
                *(float4*)(crow + cb * 32 + 4 * e) = make_float4(
                    __uint_as_float(r[4*e+0]), __uint_as_float(r[4*e+1]),
                    __uint_as_float(r[4*e+2]), __uint_as_float(r[4*e+3]));
        }
    }
    __syncthreads();
    if (wid == 0)
        asm volatile("tcgen05.dealloc.cta_group::1.sync.aligned.b32 %0, %1;"
                     :: "r"(tmem), "r"(128u));
#else
    // SIMT fallback: thread -> (token, e-half)
    const int tid = threadIdx.x;
    const int tok = row0 + (tid & 127);
    const int eb  = (tid >> 7) << 5;         // 0 or 32
    float qr[64];
    const float4* qp = (const float4*)&g_q[((long)(b * Tt + tok) * Hh + h) * DhD];
#pragma unroll
    for (int i = 0; i < 16; i++) {
        float4 w = qp[i];
        qr[4*i] = w.x; qr[4*i+1] = w.y; qr[4*i+2] = w.z; qr[4*i+3] = w.w;
    }
    float* rrow = g_R + ((long)((bh * 7 + s) * Tt + tok)) * DhD;
    for (int e = eb; e < eb + 32; e++) {
        const __nv_bfloat16* ch = g_cSthi + ((long)((bh * 7 + s) * DhD + e)) * DhD;
        const __nv_bfloat16* cl = g_cStlo + ((long)((bh * 7 + s) * DhD + e)) * DhD;
        float a = 0.f;
#pragma unroll
        for (int d = 0; d < 64; d++)
            a += qr[d] * (__bfloat162float(ch[d]) + __bfloat162float(cl[d]));
        rrow[e] = a;
    }
#endif
}

// ---------------- attention/mixing (256 threads; cached part reads g_R) -----
__global__ __launch_bounds__(256) void attn_kernel()
{
    const int bx  = blockIdx.x;
    const int seg = bx & (NSEG - 1);
    const int bh  = bx >> 3;
    const int b   = bh >> 4;
    const int h   = bh & 15;
    const int t   = threadIdx.x;
    const int tg  = seg * SEG + t;
    const int cur = seg;

    __shared__ __align__(16) float Ks[64][64];
    __shared__ __align__(16) float Vs[64][64];
    __shared__ __align__(16) float Cs[8][64];
    __shared__ float Wsm[8][256];

    const long rowbase = ((long)(b * Tt + tg) * Hh + h) * DhD;

    // ---------- phase 1: scores ----------
    float sc[8];
    float ons = 0.f;
    {
        float ureg[64];
        const float4* up = (const float4*)&g_u[rowbase];
#pragma unroll
        for (int i = 0; i < 16; i++) {
            float4 w4 = up[i];
            ureg[4*i] = w4.x; ureg[4*i+1] = w4.y; ureg[4*i+2] = w4.z; ureg[4*i+3] = w4.w;
        }
        for (int i = t; i < cur * 64; i += 256)
            Cs[i >> 6][i & 63] = g_cctx[(bh * NSEG + (i >> 6)) * DhD + (i & 63)];
        __syncthreads();
#pragma unroll
        for (int s = 0; s < 8; s++) {
            float a = 0.f;
            if (s < cur) {
                const float4* cp = (const float4*)Cs[s];
#pragma unroll
                for (int j = 0; j < 16; j++) {
                    float4 c4 = cp[j];
                    a += ureg[4*j]*c4.x + ureg[4*j+1]*c4.y + ureg[4*j+2]*c4.z + ureg[4*j+3]*c4.w;
                }
            }
            sc[s] = a;
        }
        for (int tile = 0; tile < 4; tile++) {
            __syncthreads();
            for (int i = t; i < 1024; i += 256) {
                int tok = i >> 4, c4 = (i & 15) << 2;
                long g = ((long)(b * Tt + seg * SEG + tile * 64 + tok) * Hh + h) * DhD + c4;
                *(float4*)&Ks[tok][c4] = *(const float4*)&g_k[g];
            }
            __syncthreads();
            int lim = t - tile * 64;
            if (lim >= 0) {
                int n = lim < 63 ? lim : 63;
                for (int tp = 0; tp <= n; tp++) {
                    const float4* kr = (const float4*)Ks[tp];
                    float a = 0.f;
#pragma unroll
                    for (int j = 0; j < 16; j++) {
                        float4 k4 = kr[j];
                        a += ureg[4*j]*k4.x + ureg[4*j+1]*k4.y + ureg[4*j+2]*k4.z + ureg[4*j+3]*k4.w;
                    }
                    ons += a;
                }
            }
        }
    }

    // ---------- softmax ----------
    float wcur;
    if (cur == 0) {
        wcur = 1.f;
    } else {
        float m = ons;
#pragma unroll
        for (int s = 0; s < 8; s++) if (s < cur && sc[s] > m) m = sc[s];
        float eon = expf(ons - m);
        float denom = eon;
#pragma unroll
        for (int s = 0; s < 8; s++) {
            if (s < cur) { float e = expf(sc[s] - m); sc[s] = e; denom += e; }
        }
        float inv = 1.f / denom;
        wcur = eon * inv;
#pragma unroll
        for (int s = 0; s < 8; s++)
            if (s < cur) Wsm[s][t] = sc[s] * inv + ((s == cur - 1) ? wcur : 0.f);
    }

    // ---------- phase 2: output ----------
    float4 q4r[16];
    {
        const float4* qp = (const float4*)&g_q[rowbase];
#pragma unroll
        for (int i = 0; i < 16; i++) q4r[i] = qp[i];
    }
    float outr[64];
#pragma unroll
    for (int i = 0; i < 64; i++) outr[i] = 0.f;

    // cached-S contributions via precomputed R (tensor-core output)
    for (int s = 0; s < cur; s++) {
        float ws = Wsm[s][t];
        const float4* rp =
            (const float4*)(g_R + ((long)((bh * 7 + s) * Tt + tg)) * DhD);
#pragma unroll
        for (int e = 0; e < 16; e++) {
            float4 r4 = rp[e];
            outr[4*e+0] += ws * r4.x;
            outr[4*e+1] += ws * r4.y;
            outr[4*e+2] += ws * r4.z;
            outr[4*e+3] += ws * r4.w;
        }
    }

    // intra-segment causal part
    for (int tile = 0; tile < 4; tile++) {
        __syncthreads();
        for (int i = t; i < 1024; i += 256) {
            int tok = i >> 4, c4 = (i & 15) << 2;
            long g = ((long)(b * Tt + seg * SEG + tile * 64 + tok) * Hh + h) * DhD + c4;
            *(float4*)&Ks[tok][c4] = *(const float4*)&g_k[g];
            *(float4*)&Vs[tok][c4] = *(const float4*)&g_v[g];
        }
        __syncthreads();
        int lim = t - tile * 64;
        if (lim >= 0) {
            int n = lim < 63 ? lim : 63;
            for (int tp = 0; tp <= n; tp++) {
                const float4* kr = (const float4*)Ks[tp];
                float a = 0.f;
#pragma unroll
                for (int j = 0; j < 16; j++) {
                    float4 k4 = kr[j];
                    a += q4r[j].x*k4.x + q4r[j].y*k4.y + q4r[j].z*k4.z + q4r[j].w*k4.w;
                }
                float f = wcur * a;
                const float4* vr = (const float4*)Vs[tp];
#pragma unroll
                for (int e = 0; e < 16; e++) {
                    float4 v4 = vr[e];
                    outr[4*e+0] += f * v4.x;
                    outr[4*e+1] += f * v4.y;
                    outr[4*e+2] += f * v4.z;
                    outr[4*e+3] += f * v4.w;
                }
            }
        }
    }

    float4* yp = (float4*)&g_y[rowbase];
#pragma unroll
    for (int e = 0; e < 16; e++)
        yp[e] = make_float4(outr[4*e], outr[4*e+1], outr[4*e+2], outr[4*e+3]);
}

// ---------------- launch ----------------------------------------------------
extern "C" void kernel_launch(void* const* d_in, const int* in_sizes, int n_in,
                              void* d_out, int out_size)
{
    const float* x  = (const float*)d_in[0];
    const float* Wq = (const float*)d_in[1];
    const float* Wk = (const float*)d_in[2];
    const float* Wv = (const float*)d_in[3];
    const float* Wu = (const float*)d_in[4];
    const float* Wo = (const float*)d_in[5];
    float* out = (float*)d_out;

    __nv_bfloat16 *pxh, *pxl, *pyh, *pyl, *pqh, *pql;
    float *pyf, *pqf;
    cudaGetSymbolAddress((void**)&pxh, g_xhi);
    cudaGetSymbolAddress((void**)&pxl, g_xlo);
    cudaGetSymbolAddress((void**)&pyh, g_yhi);
    cudaGetSymbolAddress((void**)&pyl, g_ylo);
    cudaGetSymbolAddress((void**)&pqh, g_qhi);
    cudaGetSymbolAddress((void**)&pql, g_qlo);
    cudaGetSymbolAddress((void**)&pyf, g_y);
    cudaGetSymbolAddress((void**)&pqf, g_q);

    cudaFuncSetAttribute(proj4_tc,      cudaFuncAttributeMaxDynamicSharedMemorySize, DYN_SMEM);
    cudaFuncSetAttribute(gemm_out_tc,   cudaFuncAttributeMaxDynamicSharedMemorySize, DYN_SMEM);
    cudaFuncSetAttribute(attn_R_kernel, cudaFuncAttributeMaxDynamicSharedMemorySize, AR_SMEM);

    const int N4 = BT * Dd / 4;
    cvt_split<<<N4 / 256, 256>>>((const float4*)x, pxh, pxl, N4);

    dim3 gw(16, 16, 5);
    cvt_wt<<<gw, 256>>>(Wq, Wk, Wv, Wu, Wo);

    dim3 gp(Dd / 128, BT / 128, 4);                // (8, 64, 4)
    proj4_tc<<<gp, 256, DYN_SMEM>>>();

    cvt_split<<<N4 / 256, 256>>>((const float4*)pqf, pqh, pql, N4);

    seg_sums  <<<BH * NSEG, 256>>>();
    seg_prefix<<<BH,        256>>>();

    dim3 gr(14, 7, BH);                            // (mt, s, bh)
    attn_R_kernel<<<gr, 256, AR_SMEM>>>();

    attn_kernel<<<BH * NSEG, 256>>>();

    cvt_split<<<N4 / 256, 256>>>((const float4*)pyf, pyh, pyl, N4);

    dim3 gg(Dd / 128, BT / 128);                   // (8, 64)
    gemm_out_tc<<<gg, 256, DYN_SMEM>>>(out);
}

// round 17
// speedup vs baseline: 1.1256x; 1.0741x over previous
#include <cuda_runtime.h>
#include <cuda_bf16.h>
#include <math.h>
#include <stdint.h>

#define Bb   4
#define Tt   2048
#define Dd   1024
#define Hh   16
#define DhD  64
#define SEG  256
#define NSEG 8
#define BT   (Bb*Tt)      // 8192
#define BH   (Bb*Hh)      // 64

#define SWZ(o) ((o) ^ ((((o) >> 3)) & 0x70))

// idesc kind::f16 cg1: F32 accum, BF16 a/b
#define IDESC     0x8200490u   // M=128, N=128
#define IDESC_N64 0x8100490u   // M=128, N=64

// tcgen05 is only available on arch-SPECIFIC targets (sm_103a / sm_100a).
#if defined(__CUDA_ARCH_FEAT_SM103_ALL) || defined(__CUDA_ARCH_FEAT_SM100_ALL) || defined(__CUDA_ARCH_SPECIFIC__)
#define TC_OK 1
#else
#define TC_OK 0
#endif

// ---------------- scratch (device globals; no allocations allowed) ----------
__device__ __align__(16) float g_q[BT*Dd];
__device__ __align__(16) float g_k[BT*Dd];
__device__ __align__(16) float g_v[BT*Dd];
__device__ __align__(16) float g_u[BT*Dd];
__device__ __align__(16) float g_y[BT*Dd];
__device__ __align__(16) float g_Schunk[(long)BH*32*DhD*DhD]; // per-64-chunk k(x)v sums
__device__ __align__(16) float g_cctx[BH*NSEG*DhD];

// bf16 split operands (weights stored TRANSPOSED: [N][K] K-major)
__device__ __align__(16) __nv_bfloat16 g_xhi[BT*Dd];
__device__ __align__(16) __nv_bfloat16 g_xlo[BT*Dd];
__device__ __align__(16) __nv_bfloat16 g_yhi[BT*Dd];
__device__ __align__(16) __nv_bfloat16 g_ylo[BT*Dd];
__device__ __align__(16) __nv_bfloat16 g_qhi[BT*Dd];
__device__ __align__(16) __nv_bfloat16 g_qlo[BT*Dd];
__device__ __align__(16) __nv_bfloat16 g_whi[5*Dd*Dd];
__device__ __align__(16) __nv_bfloat16 g_wlo[5*Dd*Dd];

// Gt[bh][ci] (ci=0..31): EXCLUSIVE global chunk-prefix, transposed [e][d], bf16.
// cS[s] == Gt[4s+4] (s=0..6).
__device__ __align__(16) __nv_bfloat16 g_Gthi[(long)BH*32*DhD*DhD];
__device__ __align__(16) __nv_bfloat16 g_Gtlo[(long)BH*32*DhD*DhD];
// R[bh][s][tok][e] = q_tok @ cS[s]   (valid for tok in segments > s)
__device__ __align__(16) float g_R[(long)BH*7*Tt*DhD];
// R2[bh][tok][e] = q_tok @ G_{chunk(tok)}
__device__ __align__(16) float g_R2[(long)BH*Tt*DhD];

// ---------------- small helpers ---------------------------------------------
__device__ __forceinline__ uint32_t smem_u32(const void* p) {
    uint32_t a;
    asm("{ .reg .u64 t; cvta.to.shared.u64 t, %1; cvt.u32.u64 %0, t; }"
        : "=r"(a) : "l"(p));
    return a;
}

__device__ __forceinline__ void cp16(uint32_t saddr, const void* gptr) {
    asm volatile("cp.async.cg.shared.global [%0], [%1], 16;"
                 :: "r"(saddr), "l"(gptr));
}

#if TC_OK
__device__ __forceinline__ void mma_f16_ss(uint32_t d, uint64_t ad, uint64_t bd,
                                           uint32_t idesc, uint32_t en) {
    asm volatile(
        "{\n\t.reg .pred p;\n\tsetp.ne.u32 p, %5, 0;\n\t"
        "tcgen05.mma.cta_group::1.kind::f16 [%0], %1, %2, %3, {%4,%4,%4,%4}, p;\n\t}"
        :: "r"(d), "l"(ad), "l"(bd), "r"(idesc), "r"(0u), "r"(en) : "memory");
}

__device__ __forceinline__ void mbar_wait(uint32_t mbar, int parity) {
    asm volatile(
        "{\n\t.reg .pred P;\n\t"
        "LAB_%=:\n\t"
        "mbarrier.try_wait.parity.acquire.cta.shared::cta.b64 P, [%0], %1;\n\t"
        "@!P bra LAB_%=;\n\t}"
        :: "r"(mbar), "r"(parity) : "memory");
}

__device__ __forceinline__ void ldtm32(uint32_t* r, uint32_t addr) {
    asm volatile(
        "tcgen05.ld.sync.aligned.32x32b.x32.b32 "
        "{%0, %1, %2, %3, %4, %5, %6, %7, "
        " %8, %9, %10, %11, %12, %13, %14, %15, "
        " %16, %17, %18, %19, %20, %21, %22, %23, "
        " %24, %25, %26, %27, %28, %29, %30, %31}, [%32];"
        : "=r"(r[0]),  "=r"(r[1]),  "=r"(r[2]),  "=r"(r[3]),
          "=r"(r[4]),  "=r"(r[5]),  "=r"(r[6]),  "=r"(r[7]),
          "=r"(r[8]),  "=r"(r[9]),  "=r"(r[10]), "=r"(r[11]),
          "=r"(r[12]), "=r"(r[13]), "=r"(r[14]), "=r"(r[15]),
          "=r"(r[16]), "=r"(r[17]), "=r"(r[18]), "=r"(r[19]),
          "=r"(r[20]), "=r"(r[21]), "=r"(r[22]), "=r"(r[23]),
          "=r"(r[24]), "=r"(r[25]), "=r"(r[26]), "=r"(r[27]),
          "=r"(r[28]), "=r"(r[29]), "=r"(r[30]), "=r"(r[31])
        : "r"(addr));
}
#endif

// ---------------- fp32 -> (bf16 hi, bf16 lo) split ---------------------------
__global__ __launch_bounds__(256) void cvt_split(
    const float4* __restrict__ in,
    __nv_bfloat16* __restrict__ hi, __nv_bfloat16* __restrict__ lo, int n4)
{
    int i = blockIdx.x * 256 + threadIdx.x;
    if (i >= n4) return;
    float4 v = in[i];
    __nv_bfloat162 h01, h23, l01, l23;
    h01.x = __float2bfloat16(v.x);
    h01.y = __float2bfloat16(v.y);
    h23.x = __float2bfloat16(v.z);
    h23.y = __float2bfloat16(v.w);
    l01.x = __float2bfloat16(v.x - __bfloat162float(h01.x));
    l01.y = __float2bfloat16(v.y - __bfloat162float(h01.y));
    l23.x = __float2bfloat16(v.z - __bfloat162float(h23.x));
    l23.y = __float2bfloat16(v.w - __bfloat162float(h23.y));
    ((__nv_bfloat162*)&hi[4*i])[0] = h01;
    ((__nv_bfloat162*)&hi[4*i])[1] = h23;
    ((__nv_bfloat162*)&lo[4*i])[0] = l01;
    ((__nv_bfloat162*)&lo[4*i])[1] = l23;
}

// ---------------- weight split + transpose: W[K][N] -> Wt[N][K] hi/lo -------
__global__ __launch_bounds__(256) void cvt_wt(
    const float* __restrict__ Wq, const float* __restrict__ Wk,
    const float* __restrict__ Wv, const float* __restrict__ Wu,
    const float* __restrict__ Wo)
{
    __shared__ float ts[64 * 65];
    const int wsel = blockIdx.z;
    const float* W = (wsel == 0) ? Wq : (wsel == 1) ? Wk :
                     (wsel == 2) ? Wv : (wsel == 3) ? Wu : Wo;
    const int k0 = blockIdx.y * 64, n0 = blockIdx.x * 64;

    for (int i = threadIdx.x; i < 4096; i += 256) {
        int r = i >> 6, c = i & 63;
        ts[r * 65 + c] = W[(long)(k0 + r) * Dd + n0 + c];
    }
    __syncthreads();

    const long obase = (long)wsel * Dd * Dd;
    for (int task = threadIdx.x; task < 512; task += 256) {
        int j  = task >> 3;
        int g8 = task & 7;
        __nv_bfloat16 hi8[8], lo8[8];
#pragma unroll
        for (int e = 0; e < 8; e++) {
            float f = ts[(g8 * 8 + e) * 65 + j];
            __nv_bfloat16 h = __float2bfloat16(f);
            hi8[e] = h;
            lo8[e] = __float2bfloat16(f - __bfloat162float(h));
        }
        long o = obase + (long)(n0 + j) * Dd + k0 + g8 * 8;
        *(uint4*)&g_whi[o] = *(uint4*)hi8;
        *(uint4*)&g_wlo[o] = *(uint4*)lo8;
    }
}

// ---------------- GEMM: C[128x128 tile] = A @ Bt^T ---------------------------
#define CHUNKS     16
#define STAGES     3
#define TILE_BYTES 16384          // 128 rows x 128B
#define STAGE_BYTES (4*TILE_BYTES)
#define DYN_SMEM   (STAGES*STAGE_BYTES + 1024)

__device__ __forceinline__ void gemm_tc_body(
    const __nv_bfloat16* __restrict__ Ah, const __nv_bfloat16* __restrict__ Al,
    const __nv_bfloat16* __restrict__ Bh, const __nv_bfloat16* __restrict__ Bl,
    float* __restrict__ C, int brow, int bcol)
{
#if TC_OK
    extern __shared__ __align__(16) char dynsm[];
    __shared__ __align__(8) uint64_t s_mbar[STAGES];
    __shared__ uint32_t s_tmem[1];

    char* tiles_p = (char*)(((uintptr_t)dynsm + 1023) & ~(uintptr_t)1023);
    const uint32_t tiles_u = smem_u32(tiles_p);
    const int tid  = threadIdx.x;
    const int wid  = tid >> 5;
    const int lane = tid & 31;

    if (wid == 0)
        asm volatile("tcgen05.alloc.cta_group::1.sync.aligned.shared::cta.b32 [%0], %1;"
                     :: "r"(smem_u32(s_tmem)), "r"(128u) : "memory");
    if (tid == 0) {
#pragma unroll
        for (int b = 0; b < STAGES; b++)
            asm volatile("mbarrier.init.shared.b64 [%0], %1;"
                         :: "r"(smem_u32(&s_mbar[b])), "r"(1u) : "memory");
    }
    __syncthreads();
    uint32_t tmem;
    asm volatile("ld.shared.b32 %0, [%1];" : "=r"(tmem) : "r"(smem_u32(s_tmem)));

    const uint64_t DESC_BASE =
        (2ull << 61) | (1ull << 46) | (64ull << 32) | (1ull << 16);

    const int l_row = tid >> 1;
    const int l_cb0 = (tid & 1) << 5;
    int ph[STAGES];
#pragma unroll
    for (int b = 0; b < STAGES; b++) ph[b] = 0;

    auto issue_load = [&](int c) {
        const uint32_t pu = tiles_u + (c % STAGES) * STAGE_BYTES;
        const int k0 = c * 64;
        const __nv_bfloat16* s0 = Ah + (long)(brow + l_row) * Dd + k0;
        const __nv_bfloat16* s1 = Al + (long)(brow + l_row) * Dd + k0;
        const __nv_bfloat16* s2 = Bh + (long)(bcol + l_row) * Dd + k0;
        const __nv_bfloat16* s3 = Bl + (long)(bcol + l_row) * Dd + k0;
#pragma unroll
        for (int j = 0; j < 4; j++) {
            int cb = l_cb0 + ((j & 1) << 4) + ((j >> 1) << 6);
            uint32_t so = SWZ(l_row * 128 + cb);
            int ce = cb >> 1;
            cp16(pu + 0 * TILE_BYTES + so, s0 + ce);
            cp16(pu + 1 * TILE_BYTES + so, s1 + ce);
            cp16(pu + 2 * TILE_BYTES + so, s2 + ce);
            cp16(pu + 3 * TILE_BYTES + so, s3 + ce);
        }
        asm volatile("cp.async.commit_group;" ::: "memory");
    };

#pragma unroll
    for (int p = 0; p < STAGES; p++) issue_load(p);

    for (int c = 0; c < CHUNKS; c++) {
        const int buf = c % STAGES;
        asm volatile("cp.async.wait_group %0;" :: "n"(STAGES - 1) : "memory");
        asm volatile("fence.proxy.async.shared::cta;" ::: "memory");
        __syncthreads();

        if (tid == 0) {
            uint32_t tb = tiles_u + buf * STAGE_BYTES;
            uint64_t adh = DESC_BASE | (uint64_t)(((tb + 0 * TILE_BYTES) >> 4) & 0x3FFF);
            uint64_t adl = DESC_BASE | (uint64_t)(((tb + 1 * TILE_BYTES) >> 4) & 0x3FFF);
            uint64_t bdh = DESC_BASE | (uint64_t)(((tb + 2 * TILE_BYTES) >> 4) & 0x3FFF);
            uint64_t bdl = DESC_BASE | (uint64_t)(((tb + 3 * TILE_BYTES) >> 4) & 0x3FFF);
#pragma unroll
            for (int k = 0; k < 4; k++) {
                uint32_t en0 = (c > 0 || k > 0) ? 1u : 0u;
                mma_f16_ss(tmem, adh + 2 * k, bdh + 2 * k, IDESC, en0);
                mma_f16_ss(tmem, adh + 2 * k, bdl + 2 * k, IDESC, 1u);
                mma_f16_ss(tmem, adl + 2 * k, bdh + 2 * k, IDESC, 1u);
            }
            asm volatile(
                "tcgen05.commit.cta_group::1.mbarrier::arrive::one.shared::cluster.b64 [%0];"
                :: "r"(smem_u32(&s_mbar[buf])) : "memory");
        }

        mbar_wait(smem_u32(&s_mbar[buf]), ph[buf]);
        ph[buf] ^= 1;

        if (c + STAGES < CHUNKS)
            issue_load(c + STAGES);
        else
            asm volatile("cp.async.commit_group;" ::: "memory");
    }

    asm volatile("tcgen05.fence::after_thread_sync;" ::: "memory");

    if (wid < 4) {
        int row = brow + wid * 32 + lane;
#pragma unroll
        for (int cb = 0; cb < 4; cb++) {
            uint32_t r[32];
            ldtm32(r, tmem + cb * 32);
            asm volatile("tcgen05.wait::ld.sync.aligned;" ::: "memory");
            float* crow = C + (long)row * Dd + bcol + cb * 32;
#pragma unroll
            for (int e = 0; e < 8; e++)
                *(float4*)(crow + 4 * e) = make_float4(
                    __uint_as_float(r[4*e+0]), __uint_as_float(r[4*e+1]),
                    __uint_as_float(r[4*e+2]), __uint_as_float(r[4*e+3]));
        }
    }
    __syncthreads();
    if (wid == 0)
        asm volatile("tcgen05.dealloc.cta_group::1.sync.aligned.b32 %0, %1;"
                     :: "r"(tmem), "r"(128u));
#else
    // ---------------- SIMT fallback (base-family target) -------------------
    __shared__ __align__(16) float As[8][128];
    __shared__ __align__(16) float Bs[8][128];

    const int tid  = threadIdx.x;
    const int trow = (tid >> 4) << 2;
    const int tcol = (tid & 15) << 2;

    float acc[8][8];
#pragma unroll
    for (int i = 0; i < 8; i++)
#pragma unroll
        for (int j = 0; j < 8; j++) acc[i][j] = 0.f;

    const int  lrow = tid & 127;
    const bool isB  = tid >= 128;
    const __nv_bfloat16* hsrc = isB ? (Bh + (long)(bcol + lrow) * Dd)
                                    : (Ah + (long)(brow + lrow) * Dd);
    const __nv_bfloat16* lsrc = isB ? (Bl + (long)(bcol + lrow) * Dd)
                                    : (Al + (long)(brow + lrow) * Dd);

    for (int k0 = 0; k0 < Dd; k0 += 8) {
        __syncthreads();
        uint4 hraw = *(const uint4*)(hsrc + k0);
        uint4 lraw = *(const uint4*)(lsrc + k0);
        const __nv_bfloat16* h8 = (const __nv_bfloat16*)&hraw;
        const __nv_bfloat16* l8 = (const __nv_bfloat16*)&lraw;
        float (*dst)[128] = isB ? Bs : As;
#pragma unroll
        for (int e = 0; e < 8; e++)
            dst[e][lrow] = __bfloat162float(h8[e]) + __bfloat162float(l8[e]);
        __syncthreads();
#pragma unroll
        for (int kk = 0; kk < 8; kk++) {
            float4 a0 = *(const float4*)&As[kk][trow];
            float4 a1 = *(const float4*)&As[kk][64 + trow];
            float4 b0 = *(const float4*)&Bs[kk][tcol];
            float4 b1 = *(const float4*)&Bs[kk][64 + tcol];
            float ar[8] = {a0.x,a0.y,a0.z,a0.w, a1.x,a1.y,a1.z,a1.w};
            float br[8] = {b0.x,b0.y,b0.z,b0.w, b1.x,b1.y,b1.z,b1.w};
#pragma unroll
            for (int i = 0; i < 8; i++)
#pragma unroll
                for (int j = 0; j < 8; j++) acc[i][j] += ar[i] * br[j];
        }
    }

#pragma unroll
    for (int i = 0; i < 8; i++) {
        int r = brow + ((i < 4) ? (trow + i) : (64 + trow + i - 4));
        float4 c0 = make_float4(acc[i][0], acc[i][1], acc[i][2], acc[i][3]);
        float4 c1 = make_float4(acc[i][4], acc[i][5], acc[i][6], acc[i][7]);
        *(float4*)&C[(long)r * Dd + bcol + tcol]      = c0;
        *(float4*)&C[(long)r * Dd + bcol + 64 + tcol] = c1;
    }
#endif
}

__global__ __launch_bounds__(256) void proj4_tc()
{
    int z = blockIdx.z;
    const __nv_bfloat16* Bh = g_whi + (long)z * Dd * Dd;
    const __nv_bfloat16* Bl = g_wlo + (long)z * Dd * Dd;
    float* Cd = (z == 0) ? g_q : (z == 1) ? g_k : (z == 2) ? g_v : g_u;
    gemm_tc_body(g_xhi, g_xlo, Bh, Bl, Cd, blockIdx.y * 128, blockIdx.x * 128);
}

__global__ __launch_bounds__(256) void gemm_out_tc(float* __restrict__ out)
{
    gemm_tc_body(g_yhi, g_ylo, g_whi + 4l * Dd * Dd, g_wlo + 4l * Dd * Dd,
                 out, blockIdx.y * 128, blockIdx.x * 128);
}

// ---------------- per-chunk sums (cp.async double-buffered) -----------------
// Emits per-64-token-chunk k(x)v sums (4/seg) + per-seg k sum (cctx).
__global__ __launch_bounds__(256) void seg_sums()
{
    const int bx = blockIdx.x;
    const int s  = bx & (NSEG - 1);
    const int bh = bx >> 3;
    const int b  = bh >> 4;
    const int h  = bh & 15;
    const int tid = threadIdx.x;
    const int d  = tid >> 2;
    const int e0 = (tid & 3) << 4;

    __shared__ __align__(16) float Ks[2][32][64];
    __shared__ __align__(16) float Vs[2][32][64];

    float acc[16];
#pragma unroll
    for (int i = 0; i < 16; i++) acc[i] = 0.f;
    float ctx = 0.f;

    auto issue = [&](int it) {
        int buf = it & 1;
        for (int i = tid; i < 512; i += 256) {
            int tok = i >> 4, c4 = (i & 15) << 2;
            long g = ((long)(b * Tt + s * SEG + it * 32 + tok) * Hh + h) * DhD + c4;
            cp16(smem_u32(&Ks[buf][tok][c4]), &g_k[g]);
            cp16(smem_u32(&Vs[buf][tok][c4]), &g_v[g]);
        }
        asm volatile("cp.async.commit_group;" ::: "memory");
    };

    issue(0);
    for (int it = 0; it < 8; it++) {
        if (it + 1 < 8) issue(it + 1);
        else asm volatile("cp.async.commit_group;" ::: "memory");
        asm volatile("cp.async.wait_group 1;" ::: "memory");
        __syncthreads();
        const int buf = it & 1;
#pragma unroll
        for (int j = 0; j < 32; j++) {
            float kd = Ks[buf][j][d];
            ctx += kd;
            const float4* vr = (const float4*)&Vs[buf][j][e0];
#pragma unroll
            for (int q4 = 0; q4 < 4; q4++) {
                float4 vv = vr[q4];
                acc[4*q4+0] += kd * vv.x;
                acc[4*q4+1] += kd * vv.y;
                acc[4*q4+2] += kd * vv.z;
                acc[4*q4+3] += kd * vv.w;
            }
        }
        if (it & 1) {   // end of a 64-token chunk
            int cch = it >> 1;
            long base = ((long)((bh * NSEG + s) * 4 + cch) * DhD + d) * DhD + e0;
#pragma unroll
            for (int q4 = 0; q4 < 4; q4++) {
                *(float4*)&g_Schunk[base + 4*q4] =
                    make_float4(acc[4*q4], acc[4*q4+1], acc[4*q4+2], acc[4*q4+3]);
                acc[4*q4] = acc[4*q4+1] = acc[4*q4+2] = acc[4*q4+3] = 0.f;
            }
        }
        __syncthreads();
    }
    if ((tid & 3) == 0) g_cctx[(bh * NSEG + s) * DhD + d] = ctx;
}

// ---------------- chunk-prefix scan -> transposed bf16 Gt -------------------
// Gt[ci] = transpose(sum of chunks < ci), ci = 0..31.
__global__ __launch_bounds__(256) void seg_prefix()
{
    __shared__ float run[64 * 65];
    const int bh = blockIdx.x;

    for (int i = threadIdx.x; i < 4096; i += 256)
        run[(i >> 6) * 65 + (i & 63)] = 0.f;
    __syncthreads();

    for (int ci = 0; ci < 32; ci++) {
        for (int j = threadIdx.x; j < 4096; j += 256) {
            int d = j & 63, e = j >> 6;
            float v = run[d * 65 + e];
            __nv_bfloat16 hh = __float2bfloat16(v);
            long o = ((long)((bh * 32 + ci) * DhD + e)) * DhD + d;
            g_Gthi[o] = hh;
            g_Gtlo[o] = __float2bfloat16(v - __bfloat162float(hh));
        }
        __syncthreads();
        for (int i = threadIdx.x; i < 4096; i += 256)
            run[(i >> 6) * 65 + (i & 63)] +=
                g_Schunk[((long)(bh * 32 + ci)) * 4096 + i];
        __syncthreads();
    }
}

// ---------------- R GEMM: R[bh][s][tok] = q_tok @ cS[s] = q @ Gt[4s+4]^T ----
#define AR_TILE_A 16384       // 128 rows x 128B
#define AR_TILE_B 8192        // 64 rows x 128B
#define AR_SMEM   (2*AR_TILE_A + 2*AR_TILE_B + 1024)

__global__ __launch_bounds__(256) void attn_R_kernel()
{
    const int mt = blockIdx.x, s = blockIdx.y, bh = blockIdx.z;
    const int row0 = ((s + 1) * 2 + mt) * 128;
    if (row0 >= Tt) return;
    const int b = bh >> 4, h = bh & 15;
    const long gtbase = ((long)(bh * 32 + 4 * (s + 1))) * 4096;

#if TC_OK
    extern __shared__ __align__(16) char dynsm[];
    __shared__ __align__(8) uint64_t s_mbar;
    __shared__ uint32_t s_tmem[1];

    char* tp = (char*)(((uintptr_t)dynsm + 1023) & ~(uintptr_t)1023);
    const uint32_t tu = smem_u32(tp);
    const int tid  = threadIdx.x;
    const int wid  = tid >> 5;
    const int lane = tid & 31;

    if (wid == 0)
        asm volatile("tcgen05.alloc.cta_group::1.sync.aligned.shared::cta.b32 [%0], %1;"
                     :: "r"(smem_u32(s_tmem)), "r"(128u) : "memory");
    if (tid == 0)
        asm volatile("mbarrier.init.shared.b64 [%0], %1;"
                     :: "r"(smem_u32(&s_mbar)), "r"(1u) : "memory");
    __syncthreads();
    uint32_t tmem;
    asm volatile("ld.shared.b32 %0, [%1];" : "=r"(tmem) : "r"(smem_u32(s_tmem)));

    const uint64_t DESC_BASE =
        (2ull << 61) | (1ull << 46) | (64ull << 32) | (1ull << 16);

    for (int i = tid; i < 1024; i += 256) {
        int row = i >> 3, cb = (i & 7) << 4;
        uint32_t so = SWZ(row * 128 + cb);
        long ga = ((long)(b * Tt + row0 + row) * Hh + h) * DhD + (cb >> 1);
        cp16(tu + so, g_qhi + ga);
        cp16(tu + AR_TILE_A + so, g_qlo + ga);
    }
    for (int i = tid; i < 512; i += 256) {
        int row = i >> 3, cb = (i & 7) << 4;
        uint32_t so = SWZ(row * 128 + cb);
        long gb = gtbase + (long)row * DhD + (cb >> 1);
        cp16(tu + 2 * AR_TILE_A + so, g_Gthi + gb);
        cp16(tu + 2 * AR_TILE_A + AR_TILE_B + so, g_Gtlo + gb);
    }
    asm volatile("cp.async.commit_group;" ::: "memory");
    asm volatile("cp.async.wait_group 0;" ::: "memory");
    asm volatile("fence.proxy.async.shared::cta;" ::: "memory");
    __syncthreads();

    if (tid == 0) {
        uint64_t adh = DESC_BASE | (uint64_t)((tu >> 4) & 0x3FFF);
        uint64_t adl = DESC_BASE | (uint64_t)(((tu + AR_TILE_A) >> 4) & 0x3FFF);
        uint64_t bdh = DESC_BASE | (uint64_t)(((tu + 2 * AR_TILE_A) >> 4) & 0x3FFF);
        uint64_t bdl = DESC_BASE | (uint64_t)(((tu + 2 * AR_TILE_A + AR_TILE_B) >> 4) & 0x3FFF);
#pragma unroll
        for (int k = 0; k < 4; k++) {
            mma_f16_ss(tmem, adh + 2 * k, bdh + 2 * k, IDESC_N64, (k > 0) ? 1u : 0u);
            mma_f16_ss(tmem, adh + 2 * k, bdl + 2 * k, IDESC_N64, 1u);
            mma_f16_ss(tmem, adl + 2 * k, bdh + 2 * k, IDESC_N64, 1u);
        }
        asm volatile(
            "tcgen05.commit.cta_group::1.mbarrier::arrive::one.shared::cluster.b64 [%0];"
            :: "r"(smem_u32(&s_mbar)) : "memory");
    }
    mbar_wait(smem_u32(&s_mbar), 0);
    asm volatile("tcgen05.fence::after_thread_sync;" ::: "memory");

    if (wid < 4) {
        int tok = row0 + wid * 32 + lane;
        float* crow = g_R + ((long)((bh * 7 + s) * Tt + tok)) * DhD;
#pragma unroll
        for (int cb = 0; cb < 2; cb++) {
            uint32_t r[32];
            ldtm32(r, tmem + cb * 32);
            asm volatile("tcgen05.wait::ld.sync.aligned;" ::: "memory");
#pragma unroll
            for (int e = 0; e < 8; e++)
                *(float4*)(crow + cb * 32 + 4 * e) = make_float4(
                    __uint_as_float(r[4*e+0]), __uint_as_float(r[4*e+1]),
                    __uint_as_float(r[4*e+2]), __uint_as_float(r[4*e+3]));
        }
    }
    __syncthreads();
    if (wid == 0)
        asm volatile("tcgen05.dealloc.cta_group::1.sync.aligned.b32 %0, %1;"
                     :: "r"(tmem), "r"(128u));
#else
    const int tid = threadIdx.x;
    const int tok = row0 + (tid & 127);
    const int eb  = (tid >> 7) << 5;
    float qr[64];
    const float4* qp = (const float4*)&g_q[((long)(b * Tt + tok) * Hh + h) * DhD];
#pragma unroll
    for (int i = 0; i < 16; i++) {
        float4 w = qp[i];
        qr[4*i] = w.x; qr[4*i+1] = w.y; qr[4*i+2] = w.z; qr[4*i+3] = w.w;
    }
    float* rrow = g_R + ((long)((bh * 7 + s) * Tt + tok)) * DhD;
    for (int e = eb; e < eb + 32; e++) {
        const __nv_bfloat16* ch = g_Gthi + gtbase + (long)e * DhD;
        const __nv_bfloat16* cl = g_Gtlo + gtbase + (long)e * DhD;
        float a = 0.f;
#pragma unroll
        for (int d = 0; d < 64; d++)
            a += qr[d] * (__bfloat162float(ch[d]) + __bfloat162float(cl[d]));
        rrow[e] = a;
    }
#endif
}

// ---------------- R2 GEMM: R2[bh][tok] = q_tok @ G_{chunk(tok)} --------------
// grid (mt=2, seg=8, bh=64). M=128 tokens, B = 4 stacked Gt chunks (N=256,
// issued as 2 x N=128 MMAs). Each warp's 32 tokens share one chunk -> uniform
// TMEM column base per warp in the epilogue.
#define R2_TILE_A 16384       // 128 rows x 128B
#define R2_TILE_B 32768       // 256 rows x 128B
#define R2_SMEM   (2*R2_TILE_A + 2*R2_TILE_B + 1024)

__global__ __launch_bounds__(256) void attn_R2_kernel()
{
    const int mt = blockIdx.x, seg = blockIdx.y, bh = blockIdx.z;
    const int b = bh >> 4, h = bh & 15;
    const int row0 = seg * SEG + mt * 128;

#if TC_OK
    extern __shared__ __align__(16) char dynsm[];
    __shared__ __align__(8) uint64_t s_mbar;
    __shared__ uint32_t s_tmem[1];

    char* tp = (char*)(((uintptr_t)dynsm + 1023) & ~(uintptr_t)1023);
    const uint32_t tu = smem_u32(tp);
    const int tid  = threadIdx.x;
    const int wid  = tid >> 5;
    const int lane = tid & 31;

    if (wid == 0)
        asm volatile("tcgen05.alloc.cta_group::1.sync.aligned.shared::cta.b32 [%0], %1;"
                     :: "r"(smem_u32(s_tmem)), "r"(256u) : "memory");
    if (tid == 0)
        asm volatile("mbarrier.init.shared.b64 [%0], %1;"
                     :: "r"(smem_u32(&s_mbar)), "r"(1u) : "memory");
    __syncthreads();
    uint32_t tmem;
    asm volatile("ld.shared.b32 %0, [%1];" : "=r"(tmem) : "r"(smem_u32(s_tmem)));

    const uint64_t DESC_BASE =
        (2ull << 61) | (1ull << 46) | (64ull << 32) | (1ull << 16);

    // A: 128 q rows
    for (int i = tid; i < 1024; i += 256) {
        int row = i >> 3, cb = (i & 7) << 4;
        uint32_t so = SWZ(row * 128 + cb);
        long ga = ((long)(b * Tt + row0 + row) * Hh + h) * DhD + (cb >> 1);
        cp16(tu + so, g_qhi + ga);
        cp16(tu + R2_TILE_A + so, g_qlo + ga);
    }
    // B: 256 rows = Gt chunks 4*seg .. 4*seg+3
    for (int i = tid; i < 2048; i += 256) {
        int r = i >> 3, cb = (i & 7) << 4;
        uint32_t so = SWZ(r * 128 + cb);
        long gb = ((long)((bh * 32 + seg * 4 + (r >> 6)) * DhD + (r & 63))) * DhD + (cb >> 1);
        cp16(tu + 2 * R2_TILE_A + so, g_Gthi + gb);
        cp16(tu + 2 * R2_TILE_A + R2_TILE_B + so, g_Gtlo + gb);
    }
    asm volatile("cp.async.commit_group;" ::: "memory");
    asm volatile("cp.async.wait_group 0;" ::: "memory");
    asm volatile("fence.proxy.async.shared::cta;" ::: "memory");
    __syncthreads();

    if (tid == 0) {
        uint64_t adh = DESC_BASE | (uint64_t)((tu >> 4) & 0x3FFF);
        uint64_t adl = DESC_BASE | (uint64_t)(((tu + R2_TILE_A) >> 4) & 0x3FFF);
#pragma unroll
        for (int half = 0; half < 2; half++) {
            uint32_t bb = tu + 2 * R2_TILE_A + half * 16384;
            uint64_t bdh = DESC_BASE | (uint64_t)((bb >> 4) & 0x3FFF);
            uint64_t bdl = DESC_BASE | (uint64_t)(((bb + R2_TILE_B) >> 4) & 0x3FFF);
            uint32_t dtm = tmem + half * 128;
#pragma unroll
            for (int k = 0; k < 4; k++) {
                mma_f16_ss(dtm, adh + 2 * k, bdh + 2 * k, IDESC, (k > 0) ? 1u : 0u);
                mma_f16_ss(dtm, adh + 2 * k, bdl + 2 * k, IDESC, 1u);
                mma_f16_ss(dtm, adl + 2 * k, bdh + 2 * k, IDESC, 1u);
            }
        }
        asm volatile(
            "tcgen05.commit.cta_group::1.mbarrier::arrive::one.shared::cluster.b64 [%0];"
            :: "r"(smem_u32(&s_mbar)) : "memory");
    }
    mbar_wait(smem_u32(&s_mbar), 0);
    asm volatile("tcgen05.fence::after_thread_sync;" ::: "memory");

    if (wid < 4) {
        int m   = wid * 32 + lane;
        int tok = row0 + m;
        int ctile = (mt * 128 + wid * 32) >> 6;   // chunk within seg, warp-uniform
        float* crow = g_R2 + ((long)(bh * Tt + tok)) * DhD;
#pragma unroll
        for (int cb = 0; cb < 2; cb++) {
            uint32_t r[32];
            ldtm32(r, tmem + ctile * 64 + cb * 32);
            asm volatile("tcgen05.wait::ld.sync.aligned;" ::: "memory");
#pragma unroll
            for (int e = 0; e < 8; e++)
                *(float4*)(crow + cb * 32 + 4 * e) = make_float4(
                    __uint_as_float(r[4*e+0]), __uint_as_float(r[4*e+1]),
                    __uint_as_float(r[4*e+2]), __uint_as_float(r[4*e+3]));
        }
    }
    __syncthreads();
    if (wid == 0)
        asm volatile("tcgen05.dealloc.cta_group::1.sync.aligned.b32 %0, %1;"
                     :: "r"(tmem), "r"(256u));
#else
    const int tid = threadIdx.x;
    const int m   = tid & 127;
    const int tok = row0 + m;
    const int eb  = (tid >> 7) << 5;
    const int chunk = seg * 4 + ((mt * 128 + m) >> 6);
    float qr[64];
    const float4* qp = (const float4*)&g_q[((long)(b * Tt + tok) * Hh + h) * DhD];
#pragma unroll
    for (int i = 0; i < 16; i++) {
        float4 w = qp[i];
        qr[4*i] = w.x; qr[4*i+1] = w.y; qr[4*i+2] = w.z; qr[4*i+3] = w.w;
    }
    float* rrow = g_R2 + ((long)(bh * Tt + tok)) * DhD;
    for (int e = eb; e < eb + 32; e++) {
        const __nv_bfloat16* ch = g_Gthi + ((long)((bh * 32 + chunk) * DhD + e)) * DhD;
        const __nv_bfloat16* cl = g_Gtlo + ((long)((bh * 32 + chunk) * DhD + e)) * DhD;
        float a = 0.f;
#pragma unroll
        for (int d = 0; d < 64; d++)
            a += qr[d] * (__bfloat162float(ch[d]) + __bfloat162float(cl[d]));
        rrow[e] = a;
    }
#endif
}

// ---------------- attention/mixing: single k/v pass, chunked prefixes -------
__global__ __launch_bounds__(256) void attn_kernel()
{
    const int bx  = blockIdx.x;
    const int seg = bx & (NSEG - 1);
    const int bh  = bx >> 3;
    const int b   = bh >> 4;
    const int h   = bh & 15;
    const int t   = threadIdx.x;
    const int tg  = seg * SEG + t;
    const int c   = t >> 6;           // chunk of this token
    const int tl  = t & 63;           // local index within chunk
    const int cur = seg;

    __shared__ __align__(16) float Ks[64][64];
    __shared__ __align__(16) float Vs[64][64];
    __shared__ __align__(16) float Cs[8][64];
    __shared__ float kbase[64];       // running sum of k over chunks < current tile

    const long rowbase = ((long)(b * Tt + tg) * Hh + h) * DhD;

    float ureg[64];
    {
        const float4* up = (const float4*)&g_u[rowbase];
#pragma unroll
        for (int i = 0; i < 16; i++) {
            float4 w4 = up[i];
            ureg[4*i] = w4.x; ureg[4*i+1] = w4.y; ureg[4*i+2] = w4.z; ureg[4*i+3] = w4.w;
        }
    }
    float4 q4r[16];
    {
        const float4* qp = (const float4*)&g_q[rowbase];
#pragma unroll
        for (int i = 0; i < 16; i++) q4r[i] = qp[i];
    }
    for (int i = t; i < cur * 64; i += 256)
        Cs[i >> 6][i & 63] = g_cctx[(bh * NSEG + (i >> 6)) * DhD + (i & 63)];
    if (t < 64) kbase[t] = 0.f;
    __syncthreads();

    // cached-seg scores
    float sc[8];
#pragma unroll
    for (int s = 0; s < 8; s++) {
        float a = 0.f;
        if (s < cur) {
            const float4* cp = (const float4*)Cs[s];
#pragma unroll
            for (int j = 0; j < 16; j++) {
                float4 c4 = cp[j];
                a += ureg[4*j]*c4.x + ureg[4*j+1]*c4.y + ureg[4*j+2]*c4.z + ureg[4*j+3]*c4.w;
            }
        }
        sc[s] = a;
    }

    // single pass over the 4 k/v tiles: ons + raw intra-chunk response
    float ons = 0.f;
    float intraraw[64];
#pragma unroll
    for (int i = 0; i < 64; i++) intraraw[i] = 0.f;

    for (int tile = 0; tile < 4; tile++) {
        __syncthreads();
        for (int i = t; i < 1024; i += 256) {
            int tok = i >> 4, c4 = (i & 15) << 2;
            long g = ((long)(b * Tt + seg * SEG + tile * 64 + tok) * Hh + h) * DhD + c4;
            *(float4*)&Ks[tok][c4] = *(const float4*)&g_k[g];
            *(float4*)&Vs[tok][c4] = *(const float4*)&g_v[g];
        }
        __syncthreads();
        if (tile == c) {
            // base: u . (sum of k over chunks < c)
            float kb = 0.f;
#pragma unroll
            for (int d = 0; d < 64; d++) kb += ureg[d] * kbase[d];
            ons += kb;
            // intra-chunk prefix (inclusive)
            for (int tp = 0; tp <= tl; tp++) {
                const float4* kr = (const float4*)Ks[tp];
                float uk = 0.f, qk = 0.f;
#pragma unroll
                for (int j = 0; j < 16; j++) {
                    float4 k4 = kr[j];
                    uk += ureg[4*j]*k4.x + ureg[4*j+1]*k4.y + ureg[4*j+2]*k4.z + ureg[4*j+3]*k4.w;
                    qk += q4r[j].x*k4.x + q4r[j].y*k4.y + q4r[j].z*k4.z + q4r[j].w*k4.w;
                }
                ons += uk;
                const float4* vr = (const float4*)Vs[tp];
#pragma unroll
                for (int e = 0; e < 16; e++) {
                    float4 v4 = vr[e];
                    intraraw[4*e+0] += qk * v4.x;
                    intraraw[4*e+1] += qk * v4.y;
                    intraraw[4*e+2] += qk * v4.z;
                    intraraw[4*e+3] += qk * v4.w;
                }
            }
        }
        __syncthreads();
        if (t < 64) {   // fold this tile into the running k-sum
            float ssum = 0.f;
#pragma unroll
            for (int j = 0; j < 64; j++) ssum += Ks[j][t];
            kbase[t] += ssum;
        }
    }

    // softmax over [sc[0..cur-1], ons]; NO folding (R2 carries cS[cur-1]+Mpre)
    float wcur;
    if (cur == 0) {
        wcur = 1.f;
    } else {
        float m = ons;
#pragma unroll
        for (int s = 0; s < 8; s++) if (s < cur && sc[s] > m) m = sc[s];
        float eon = expf(ons - m);
        float denom = eon;
#pragma unroll
        for (int s = 0; s < 8; s++) {
            if (s < cur) { float e = expf(sc[s] - m); sc[s] = e; denom += e; }
        }
        float inv = 1.f / denom;
        wcur = eon * inv;
#pragma unroll
        for (int s = 0; s < 8; s++)
            if (s < cur) sc[s] *= inv;    // sc[s] now = w_s
    }

    // combine: out = sum_s w_s * R[s] + wcur * (R2 + intraraw)
    float outr[64];
    {
        const float4* rp2 = (const float4*)(g_R2 + ((long)(bh * Tt + tg)) * DhD);
#pragma unroll
        for (int e = 0; e < 16; e++) {
            float4 r4 = rp2[e];
            outr[4*e+0] = wcur * (intraraw[4*e+0] + r4.x);
            outr[4*e+1] = wcur * (intraraw[4*e+1] + r4.y);
            outr[4*e+2] = wcur * (intraraw[4*e+2] + r4.z);
            outr[4*e+3] = wcur * (intraraw[4*e+3] + r4.w);
        }
    }
    for (int s = 0; s < cur; s++) {
        float ws = sc[s];
        const float4* rp =
            (const float4*)(g_R + ((long)((bh * 7 + s) * Tt + tg)) * DhD);
#pragma unroll
        for (int e = 0; e < 16; e++) {
            float4 r4 = rp[e];
            outr[4*e+0] += ws * r4.x;
            outr[4*e+1] += ws * r4.y;
            outr[4*e+2] += ws * r4.z;
            outr[4*e+3] += ws * r4.w;
        }
    }

    float4* yp = (float4*)&g_y[rowbase];
#pragma unroll
    for (int e = 0; e < 16; e++)
        yp[e] = make_float4(outr[4*e], outr[4*e+1], outr[4*e+2], outr[4*e+3]);
}

// ---------------- launch ----------------------------------------------------
extern "C" void kernel_launch(void* const* d_in, const int* in_sizes, int n_in,
                              void* d_out, int out_size)
{
    const float* x  = (const float*)d_in[0];
    const float* Wq = (const float*)d_in[1];
    const float* Wk = (const float*)d_in[2];
    const float* Wv = (const float*)d_in[3];
    const float* Wu = (const float*)d_in[4];
    const float* Wo = (const float*)d_in[5];
    float* out = (float*)d_out;

    __nv_bfloat16 *pxh, *pxl, *pyh, *pyl, *pqh, *pql;
    float *pyf, *pqf;
    cudaGetSymbolAddress((void**)&pxh, g_xhi);
    cudaGetSymbolAddress((void**)&pxl, g_xlo);
    cudaGetSymbolAddress((void**)&pyh, g_yhi);
    cudaGetSymbolAddress((void**)&pyl, g_ylo);
    cudaGetSymbolAddress((void**)&pqh, g_qhi);
    cudaGetSymbolAddress((void**)&pql, g_qlo);
    cudaGetSymbolAddress((void**)&pyf, g_y);
    cudaGetSymbolAddress((void**)&pqf, g_q);

    cudaFuncSetAttribute(proj4_tc,       cudaFuncAttributeMaxDynamicSharedMemorySize, DYN_SMEM);
    cudaFuncSetAttribute(gemm_out_tc,    cudaFuncAttributeMaxDynamicSharedMemorySize, DYN_SMEM);
    cudaFuncSetAttribute(attn_R_kernel,  cudaFuncAttributeMaxDynamicSharedMemorySize, AR_SMEM);
    cudaFuncSetAttribute(attn_R2_kernel, cudaFuncAttributeMaxDynamicSharedMemorySize, R2_SMEM);

    const int N4 = BT * Dd / 4;
    cvt_split<<<N4 / 256, 256>>>((const float4*)x, pxh, pxl, N4);

    dim3 gw(16, 16, 5);
    cvt_wt<<<gw, 256>>>(Wq, Wk, Wv, Wu, Wo);

    dim3 gp(Dd / 128, BT / 128, 4);                // (8, 64, 4)
    proj4_tc<<<gp, 256, DYN_SMEM>>>();

    cvt_split<<<N4 / 256, 256>>>((const float4*)pqf, pqh, pql, N4);

    seg_sums  <<<BH * NSEG, 256>>>();
    seg_prefix<<<BH,        256>>>();

    dim3 gr(14, 7, BH);                            // (mt, s, bh)
    attn_R_kernel<<<gr, 256, AR_SMEM>>>();
    dim3 g2(2, 8, BH);                             // (mt, seg, bh)
    attn_R2_kernel<<<g2, 256, R2_SMEM>>>();

    attn_kernel<<<BH * NSEG, 256>>>();

    cvt_split<<<N4 / 256, 256>>>((const float4*)pyf, pyh, pyl, N4);

    dim3 gg(Dd / 128, BT / 128);                   // (8, 64)
    gemm_out_tc<<<gg, 256, DYN_SMEM>>>(out);
}